// round 2
// baseline (speedup 1.0000x reference)
#include <cuda_runtime.h>

#define N_NODES 50000
#define N_EDGES 800000
#define CH 64
#define CH4 16
#define OUT_ELEMS (N_NODES * CH)

// ---- scratch (device globals; no allocation allowed) ----
__device__ float  g_w[2][CH * CH];            // reparameterized weights [branch][k*64+c]
__device__ float4 g_sup[2][N_NODES * CH4];    // support tensors as float4
__device__ int    g_cnt[N_NODES];
__device__ int    g_row_start[N_NODES + 1];
__device__ int    g_cursor[N_NODES];
__device__ int    g_csr_src[N_EDGES];
__device__ float  g_csr_w[N_EDGES];

// ---------------------------------------------------------------------------
// zero the per-node degree counters
// ---------------------------------------------------------------------------
__global__ __launch_bounds__(256) void zero_cnt_kernel() {
    int i = blockIdx.x * 256 + threadIdx.x;
    if (i < N_NODES) g_cnt[i] = 0;
}

// ---------------------------------------------------------------------------
// build reparameterized weights + KL sum (single block)
// ---------------------------------------------------------------------------
__global__ __launch_bounds__(256) void prep_kernel(
    const float* __restrict__ mu_m, const float* __restrict__ ls_m,
    const float* __restrict__ eps_m,
    const float* __restrict__ mu_s, const float* __restrict__ ls_s,
    const float* __restrict__ eps_s,
    float* __restrict__ kl_out)
{
    __shared__ float red[256];
    int tid = threadIdx.x;
    float acc = 0.f;
    for (int i = tid; i < CH * CH; i += 256) {
        float lm = ls_m[i], mm = mu_m[i];
        g_w[0][i] = mm + eps_m[i] * expf(lm);
        acc += 0.5f * (expf(2.f * lm) + mm * mm - 2.f * lm - 1.f);
        float lv = ls_s[i], ms = mu_s[i];
        g_w[1][i] = ms + eps_s[i] * expf(lv);
        acc += 0.5f * (expf(2.f * lv) + ms * ms - 2.f * lv - 1.f);
    }
    red[tid] = acc;
    __syncthreads();
    for (int s = 128; s > 0; s >>= 1) {
        if (tid < s) red[tid] += red[tid + s];
        __syncthreads();
    }
    if (tid == 0) kl_out[0] = red[0];
}

// ---------------------------------------------------------------------------
// register-blocked GEMM: one branch per blockIdx.y.
//   branch 0: sup_mean = mean       @ W_mean
//   branch 1: sup_var  = (std*std)  @ W_var
// Block: 64 rows x 64 cols, 256 threads, 4x4 outputs/thread, LDS.128 operands.
// X staged transposed (pitch 68 to keep float4 alignment + avoid conflicts).
// ---------------------------------------------------------------------------
#define XPITCH 68
__global__ __launch_bounds__(256) void gemm_kernel(
    const float* __restrict__ mean, const float* __restrict__ stdv)
{
    __shared__ float sXT[CH * XPITCH];   // [k][r] transposed
    __shared__ float sW[CH * CH];        // [k][c]

    int branch = blockIdx.y;
    int row0 = blockIdx.x * 64;
    int tid = threadIdx.x;

    const float4* in4 = (const float4*)(branch ? stdv : mean);
    const float4* w4  = (const float4*)g_w[branch];

    // stage weights (1024 float4)
    for (int i = tid; i < CH * CH4; i += 256)
        ((float4*)sW)[i] = w4[i];

    // stage X tile transposed (64 rows x 16 float4)
    for (int i = tid; i < 64 * CH4; i += 256) {
        int r = i >> 4, c4 = i & 15;
        int node = row0 + r;
        float4 v = make_float4(0.f, 0.f, 0.f, 0.f);
        if (node < N_NODES) v = in4[node * CH4 + c4];
        if (branch) { v.x *= v.x; v.y *= v.y; v.z *= v.z; v.w *= v.w; }
        sXT[(c4 * 4 + 0) * XPITCH + r] = v.x;
        sXT[(c4 * 4 + 1) * XPITCH + r] = v.y;
        sXT[(c4 * 4 + 2) * XPITCH + r] = v.z;
        sXT[(c4 * 4 + 3) * XPITCH + r] = v.w;
    }
    __syncthreads();

    int tr = tid >> 4;   // 0..15 row group
    int tc = tid & 15;   // 0..15 col group
    float4 a0 = make_float4(0,0,0,0), a1 = a0, a2 = a0, a3 = a0;

    #pragma unroll
    for (int k = 0; k < CH; k++) {
        float4 x = *(const float4*)&sXT[k * XPITCH + tr * 4];  // rows tr*4..+3
        float4 w = *(const float4*)&sW [k * CH     + tc * 4];  // cols tc*4..+3
        a0.x = fmaf(x.x, w.x, a0.x); a0.y = fmaf(x.x, w.y, a0.y);
        a0.z = fmaf(x.x, w.z, a0.z); a0.w = fmaf(x.x, w.w, a0.w);
        a1.x = fmaf(x.y, w.x, a1.x); a1.y = fmaf(x.y, w.y, a1.y);
        a1.z = fmaf(x.y, w.z, a1.z); a1.w = fmaf(x.y, w.w, a1.w);
        a2.x = fmaf(x.z, w.x, a2.x); a2.y = fmaf(x.z, w.y, a2.y);
        a2.z = fmaf(x.z, w.z, a2.z); a2.w = fmaf(x.z, w.w, a2.w);
        a3.x = fmaf(x.w, w.x, a3.x); a3.y = fmaf(x.w, w.y, a3.y);
        a3.z = fmaf(x.w, w.z, a3.z); a3.w = fmaf(x.w, w.w, a3.w);
    }

    float4* sup = g_sup[branch];
    int n0 = row0 + tr * 4;
    if (n0 + 0 < N_NODES) sup[(n0 + 0) * CH4 + tc] = a0;
    if (n0 + 1 < N_NODES) sup[(n0 + 1) * CH4 + tc] = a1;
    if (n0 + 2 < N_NODES) sup[(n0 + 2) * CH4 + tc] = a2;
    if (n0 + 3 < N_NODES) sup[(n0 + 3) * CH4 + tc] = a3;
}

// ---------------------------------------------------------------------------
// histogram of destination degrees
// ---------------------------------------------------------------------------
__global__ __launch_bounds__(256) void hist_kernel(const int* __restrict__ ei) {
    int e = blockIdx.x * 256 + threadIdx.x;
    if (e < N_EDGES) atomicAdd(&g_cnt[ei[N_EDGES + e]], 1);
}

// ---------------------------------------------------------------------------
// single-block exclusive scan of g_cnt -> g_row_start, g_cursor
// ---------------------------------------------------------------------------
__global__ __launch_bounds__(1024) void scan_kernel() {
    __shared__ int ss[1024];
    int tid = threadIdx.x;
    const int CHUNK = (N_NODES + 1023) / 1024;   // 49
    int base = tid * CHUNK;
    int s = 0;
    for (int i = 0; i < CHUNK; i++) {
        int idx = base + i;
        if (idx < N_NODES) s += g_cnt[idx];
    }
    ss[tid] = s;
    __syncthreads();
    for (int off = 1; off < 1024; off <<= 1) {
        int v = ss[tid];
        int a = (tid >= off) ? ss[tid - off] : 0;
        __syncthreads();
        ss[tid] = v + a;
        __syncthreads();
    }
    int run = (tid > 0) ? ss[tid - 1] : 0;
    for (int i = 0; i < CHUNK; i++) {
        int idx = base + i;
        if (idx < N_NODES) {
            g_row_start[idx] = run;
            g_cursor[idx] = run;
            run += g_cnt[idx];
        }
    }
    if (tid == 0) g_row_start[N_NODES] = N_EDGES;
}

// ---------------------------------------------------------------------------
// fill CSR: csr_src[p], csr_w[p] for edges grouped by dst
// ---------------------------------------------------------------------------
__global__ __launch_bounds__(256) void fill_kernel(
    const int* __restrict__ ei, const float* __restrict__ ew)
{
    int e = blockIdx.x * 256 + threadIdx.x;
    if (e < N_EDGES) {
        int dst = ei[N_EDGES + e];
        int p = atomicAdd(&g_cursor[dst], 1);
        g_csr_src[p] = ei[e];
        g_csr_w[p] = ew[e];
    }
}

// ---------------------------------------------------------------------------
// pull kernel: 16 lanes per node, register accumulation, single store.
// Also applies the std finalize: std = sqrt(exp(log_var) + 1e-6).
// ---------------------------------------------------------------------------
__global__ __launch_bounds__(256) void pull_kernel(
    float* __restrict__ out_mean, float* __restrict__ out_var)
{
    int tid = threadIdx.x;
    int node = blockIdx.x * 16 + (tid >> 4);
    int j = tid & 15;

    int beg = g_row_start[node];
    int end = g_row_start[node + 1];

    const float4* __restrict__ supm = g_sup[0];
    const float4* __restrict__ supv = g_sup[1];

    float4 am = make_float4(0,0,0,0);
    float4 av = make_float4(0,0,0,0);

    int k = beg;
    for (; k + 2 <= end; k += 2) {
        int   s0 = __ldg(&g_csr_src[k]);
        int   s1 = __ldg(&g_csr_src[k + 1]);
        float w0 = __ldg(&g_csr_w[k]);
        float w1 = __ldg(&g_csr_w[k + 1]);
        float4 m0 = __ldg(&supm[s0 * CH4 + j]);
        float4 m1 = __ldg(&supm[s1 * CH4 + j]);
        float4 v0 = __ldg(&supv[s0 * CH4 + j]);
        float4 v1 = __ldg(&supv[s1 * CH4 + j]);
        float q0 = w0 * w0, q1 = w1 * w1;
        am.x = fmaf(w0, m0.x, fmaf(w1, m1.x, am.x));
        am.y = fmaf(w0, m0.y, fmaf(w1, m1.y, am.y));
        am.z = fmaf(w0, m0.z, fmaf(w1, m1.z, am.z));
        am.w = fmaf(w0, m0.w, fmaf(w1, m1.w, am.w));
        av.x = fmaf(q0, v0.x, fmaf(q1, v1.x, av.x));
        av.y = fmaf(q0, v0.y, fmaf(q1, v1.y, av.y));
        av.z = fmaf(q0, v0.z, fmaf(q1, v1.z, av.z));
        av.w = fmaf(q0, v0.w, fmaf(q1, v1.w, av.w));
    }
    if (k < end) {
        int   s0 = __ldg(&g_csr_src[k]);
        float w0 = __ldg(&g_csr_w[k]);
        float q0 = w0 * w0;
        float4 m0 = __ldg(&supm[s0 * CH4 + j]);
        float4 v0 = __ldg(&supv[s0 * CH4 + j]);
        am.x = fmaf(w0, m0.x, am.x); am.y = fmaf(w0, m0.y, am.y);
        am.z = fmaf(w0, m0.z, am.z); am.w = fmaf(w0, m0.w, am.w);
        av.x = fmaf(q0, v0.x, av.x); av.y = fmaf(q0, v0.y, av.y);
        av.z = fmaf(q0, v0.z, av.z); av.w = fmaf(q0, v0.w, av.w);
    }

    ((float4*)out_mean)[node * CH4 + j] = am;

    float4 sd;
    sd.x = sqrtf(expf(av.x) + 1e-6f);
    sd.y = sqrtf(expf(av.y) + 1e-6f);
    sd.z = sqrtf(expf(av.z) + 1e-6f);
    sd.w = sqrtf(expf(av.w) + 1e-6f);
    ((float4*)out_var)[node * CH4 + j] = sd;
}

// ---------------------------------------------------------------------------
extern "C" void kernel_launch(void* const* d_in, const int* in_sizes, int n_in,
                              void* d_out, int out_size)
{
    const float* mean  = (const float*)d_in[0];   // [50000, 64]
    const float* stdv  = (const float*)d_in[1];   // [50000, 64]
    const int*   ei    = (const int*)  d_in[2];   // [2, 800000]
    const float* ew    = (const float*)d_in[3];   // [800000]
    const float* mu_m  = (const float*)d_in[4];
    const float* ls_m  = (const float*)d_in[5];
    const float* eps_m = (const float*)d_in[6];
    const float* mu_s  = (const float*)d_in[7];
    const float* ls_s  = (const float*)d_in[8];
    const float* eps_s = (const float*)d_in[9];

    float* out_mean = (float*)d_out;                   // [50000*64]
    float* out_var  = out_mean + OUT_ELEMS;            // [50000*64]
    float* kl_out   = out_mean + 2 * OUT_ELEMS;        // scalar

    // degree counters -> zero
    zero_cnt_kernel<<<(N_NODES + 255) / 256, 256>>>();
    // weights + KL
    prep_kernel<<<1, 256>>>(mu_m, ls_m, eps_m, mu_s, ls_s, eps_s, kl_out);
    // dual GEMM -> support tensors
    {
        dim3 grid((N_NODES + 63) / 64, 2);
        gemm_kernel<<<grid, 256>>>(mean, stdv);
    }
    // CSR build: histogram, scan, fill
    hist_kernel<<<(N_EDGES + 255) / 256, 256>>>(ei);
    scan_kernel<<<1, 1024>>>();
    fill_kernel<<<(N_EDGES + 255) / 256, 256>>>(ei, ew);
    // pull + finalize
    pull_kernel<<<N_NODES / 16, 256>>>(out_mean, out_var);
}

// round 3
// speedup vs baseline: 1.3936x; 1.3936x over previous
#include <cuda_runtime.h>
#include <cstdint>

#define N_NODES 50000
#define N_EDGES 800000
#define CH 64
#define CH4 16
#define OUT_ELEMS (N_NODES * CH)

// ---- scratch (device globals; no allocation allowed) ----
__device__ float  g_w[2][CH * CH];            // reparameterized weights [branch][k*64+c]
__device__ float4 g_sup[2][N_NODES * CH4];    // support tensors as float4

// ---------------------------------------------------------------------------
// Kernel 0: zero both accumulation regions of d_out (poisoned to 0xAA).
// ---------------------------------------------------------------------------
__global__ __launch_bounds__(256) void zero_kernel(float4* out4) {
    int i = blockIdx.x * 256 + threadIdx.x;
    if (i < OUT_ELEMS * 2 / 4) {
        out4[i] = make_float4(0.f, 0.f, 0.f, 0.f);
    }
}

// ---------------------------------------------------------------------------
// Kernel 1: build reparameterized weights + KL sum (single block).
// ---------------------------------------------------------------------------
__global__ __launch_bounds__(256) void prep_kernel(
    const float* __restrict__ mu_m, const float* __restrict__ ls_m,
    const float* __restrict__ eps_m,
    const float* __restrict__ mu_s, const float* __restrict__ ls_s,
    const float* __restrict__ eps_s,
    float* __restrict__ kl_out)
{
    __shared__ float red[256];
    int tid = threadIdx.x;
    float acc = 0.f;
    for (int i = tid; i < CH * CH; i += 256) {
        float lm = ls_m[i], mm = mu_m[i];
        g_w[0][i] = mm + eps_m[i] * expf(lm);
        acc += 0.5f * (expf(2.f * lm) + mm * mm - 2.f * lm - 1.f);
        float lv = ls_s[i], ms = mu_s[i];
        g_w[1][i] = ms + eps_s[i] * expf(lv);
        acc += 0.5f * (expf(2.f * lv) + ms * ms - 2.f * lv - 1.f);
    }
    red[tid] = acc;
    __syncthreads();
    for (int s = 128; s > 0; s >>= 1) {
        if (tid < s) red[tid] += red[tid + s];
        __syncthreads();
    }
    if (tid == 0) kl_out[0] = red[0];
}

// ---------------------------------------------------------------------------
// Kernel 2: register-blocked GEMM with packed f32x2 FMA (Blackwell dual-fp32).
//   branch 0: sup_mean = mean      @ W_mean
//   branch 1: sup_var  = (std*std) @ W_var
// Block: 64 rows x 64 cols, 256 threads, 4x4 outputs/thread.
// Row pairs packed into 64-bit f32x2 accumulators; x row-pair comes packed
// for free from the LDS.128 of the transposed X tile.
// ---------------------------------------------------------------------------
#define XPITCH 68
__global__ __launch_bounds__(256) void gemm_kernel(
    const float* __restrict__ mean, const float* __restrict__ stdv)
{
    __shared__ float sXT[CH * XPITCH];   // [k][r] transposed
    __shared__ float sW[CH * CH];        // [k][c]

    int branch = blockIdx.y;
    int row0 = blockIdx.x * 64;
    int tid = threadIdx.x;

    const float4* in4 = (const float4*)(branch ? stdv : mean);
    const float4* w4  = (const float4*)g_w[branch];

    // stage weights (1024 float4)
    for (int i = tid; i < CH * CH4; i += 256)
        ((float4*)sW)[i] = w4[i];

    // stage X tile transposed (64 rows x 16 float4)
    for (int i = tid; i < 64 * CH4; i += 256) {
        int r = i >> 4, c4 = i & 15;
        int node = row0 + r;
        float4 v = make_float4(0.f, 0.f, 0.f, 0.f);
        if (node < N_NODES) v = in4[node * CH4 + c4];
        if (branch) { v.x *= v.x; v.y *= v.y; v.z *= v.z; v.w *= v.w; }
        sXT[(c4 * 4 + 0) * XPITCH + r] = v.x;
        sXT[(c4 * 4 + 1) * XPITCH + r] = v.y;
        sXT[(c4 * 4 + 2) * XPITCH + r] = v.z;
        sXT[(c4 * 4 + 3) * XPITCH + r] = v.w;
    }
    __syncthreads();

    int tr = tid >> 4;   // 0..15 row group (4 rows)
    int tc = tid & 15;   // 0..15 col group (4 cols)

    // acc[p][c]: rows (tr*4+2p, tr*4+2p+1), col tc*4+c, packed f32x2
    unsigned long long acc[2][4] = {{0ull,0ull,0ull,0ull},{0ull,0ull,0ull,0ull}};

    #pragma unroll
    for (int k = 0; k < CH; k++) {
        float4 x = *(const float4*)&sXT[k * XPITCH + tr * 4];  // 4 rows at k
        float4 w = *(const float4*)&sW [k * CH     + tc * 4];  // 4 cols at k
        unsigned long long xp0, xp1;
        asm("mov.b64 %0, {%1, %2};" : "=l"(xp0) : "f"(x.x), "f"(x.y));
        asm("mov.b64 %0, {%1, %2};" : "=l"(xp1) : "f"(x.z), "f"(x.w));
        float wv[4] = {w.x, w.y, w.z, w.w};
        #pragma unroll
        for (int c = 0; c < 4; c++) {
            unsigned long long wp;
            asm("mov.b64 %0, {%1, %1};" : "=l"(wp) : "f"(wv[c]));
            asm("fma.rn.f32x2 %0, %1, %2, %0;" : "+l"(acc[0][c]) : "l"(xp0), "l"(wp));
            asm("fma.rn.f32x2 %0, %1, %2, %0;" : "+l"(acc[1][c]) : "l"(xp1), "l"(wp));
        }
    }

    float4* sup = g_sup[branch];
    #pragma unroll
    for (int p = 0; p < 2; p++) {
        float lo[4], hi[4];
        #pragma unroll
        for (int c = 0; c < 4; c++) {
            asm("mov.b64 {%0, %1}, %2;" : "=f"(lo[c]), "=f"(hi[c]) : "l"(acc[p][c]));
        }
        int n0 = row0 + tr * 4 + 2 * p;
        if (n0 < N_NODES)
            sup[n0 * CH4 + tc] = make_float4(lo[0], lo[1], lo[2], lo[3]);
        if (n0 + 1 < N_NODES)
            sup[(n0 + 1) * CH4 + tc] = make_float4(hi[0], hi[1], hi[2], hi[3]);
    }
}

// ---------------------------------------------------------------------------
// Kernel 3: edge scatter, both branches per thread.
// 16 consecutive lanes cover one edge's full 256B row per branch =>
// coalesced gathers; two red.global.add.v4 per thread (REDG floor-bound).
// ---------------------------------------------------------------------------
__global__ __launch_bounds__(256) void scatter_kernel(
    const int* __restrict__ ei, const float* __restrict__ ew,
    float* __restrict__ out_mean, float* __restrict__ out_var)
{
    int idx = blockIdx.x * 256 + threadIdx.x;          // < N_EDGES*16 = 12.8M
    int j = idx & 15;                                  // chunk within row
    int e = idx >> 4;                                  // edge

    int src = __ldg(&ei[e]);
    int dst = __ldg(&ei[N_EDGES + e]);
    float w = __ldg(&ew[e]);
    float q = w * w;

    float4 m = __ldg(&g_sup[0][src * CH4 + j]);
    float4 v = __ldg(&g_sup[1][src * CH4 + j]);

    float* am = out_mean + dst * CH + j * 4;
    float* av = out_var  + dst * CH + j * 4;
    asm volatile("red.global.add.v4.f32 [%0], {%1, %2, %3, %4};"
                 :: "l"(am), "f"(m.x * w), "f"(m.y * w), "f"(m.z * w), "f"(m.w * w)
                 : "memory");
    asm volatile("red.global.add.v4.f32 [%0], {%1, %2, %3, %4};"
                 :: "l"(av), "f"(v.x * q), "f"(v.y * q), "f"(v.z * q), "f"(v.w * q)
                 : "memory");
}

// ---------------------------------------------------------------------------
// Kernel 4: finalize std branch: std = sqrt(exp(log_var) + 1e-6), in place.
// ---------------------------------------------------------------------------
__global__ __launch_bounds__(256) void finalize_kernel(float4* __restrict__ out_var4) {
    int i = blockIdx.x * 256 + threadIdx.x;
    if (i < OUT_ELEMS / 4) {
        float4 x = out_var4[i];
        x.x = sqrtf(expf(x.x) + 1e-6f);
        x.y = sqrtf(expf(x.y) + 1e-6f);
        x.z = sqrtf(expf(x.z) + 1e-6f);
        x.w = sqrtf(expf(x.w) + 1e-6f);
        out_var4[i] = x;
    }
}

// ---------------------------------------------------------------------------
extern "C" void kernel_launch(void* const* d_in, const int* in_sizes, int n_in,
                              void* d_out, int out_size)
{
    const float* mean  = (const float*)d_in[0];   // [50000, 64]
    const float* stdv  = (const float*)d_in[1];   // [50000, 64]
    const int*   ei    = (const int*)  d_in[2];   // [2, 800000]
    const float* ew    = (const float*)d_in[3];   // [800000]
    const float* mu_m  = (const float*)d_in[4];
    const float* ls_m  = (const float*)d_in[5];
    const float* eps_m = (const float*)d_in[6];
    const float* mu_s  = (const float*)d_in[7];
    const float* ls_s  = (const float*)d_in[8];
    const float* eps_s = (const float*)d_in[9];

    float* out_mean = (float*)d_out;                   // [50000*64]
    float* out_var  = out_mean + OUT_ELEMS;            // [50000*64]
    float* kl_out   = out_mean + 2 * OUT_ELEMS;        // scalar

    // 1) zero accumulation regions
    {
        int n4 = OUT_ELEMS * 2 / 4;
        zero_kernel<<<(n4 + 255) / 256, 256>>>((float4*)d_out);
    }
    // 2) weights + KL
    prep_kernel<<<1, 256>>>(mu_m, ls_m, eps_m, mu_s, ls_s, eps_s, kl_out);
    // 3) dual GEMM -> support tensors
    {
        dim3 grid((N_NODES + 63) / 64, 2);
        gemm_kernel<<<grid, 256>>>(mean, stdv);
    }
    // 4) edge scatter (both branches per thread)
    {
        int total = N_EDGES * 16;                      // 12,800,000
        scatter_kernel<<<total / 256, 256>>>(ei, ew, out_mean, out_var);
    }
    // 5) finalize std
    {
        int n4 = OUT_ELEMS / 4;
        finalize_kernel<<<(n4 + 255) / 256, 256>>>((float4*)out_var);
    }
}

// round 4
// speedup vs baseline: 1.6126x; 1.1572x over previous
#include <cuda_runtime.h>
#include <cstdint>

#define N_NODES 50000
#define N_EDGES 800000
#define CH 64
#define CH4 16
#define OUT_ELEMS (N_NODES * CH)
#define GX 782                       // ceil(50000/64)
#define NBLOCKS (GX * 2)             // 1564
#define ZERO_FLOAT4 (OUT_ELEMS * 2 / 4)   // 1,600,000

// ---- scratch (device globals; no allocation allowed) ----
__device__ float4 g_sup[2][N_NODES * CH4];    // support tensors as float4

// ---------------------------------------------------------------------------
// Kernel 1 (fused): per block —
//   (a) zero a slice of d_out accumulation area,
//   (b) build this branch's reparameterized W into smem,
//   (c) block (0,0) additionally reduces the KL sum for BOTH branches,
//   (d) register-blocked 64x64 GEMM with packed f32x2 FMA.
//   branch 0: sup_mean = mean      @ W_mean
//   branch 1: sup_var  = (std*std) @ W_var
// ---------------------------------------------------------------------------
#define XPITCH 68
__global__ __launch_bounds__(256) void gemm_fused_kernel(
    const float* __restrict__ mean, const float* __restrict__ stdv,
    const float* __restrict__ mu_m, const float* __restrict__ ls_m,
    const float* __restrict__ eps_m,
    const float* __restrict__ mu_s, const float* __restrict__ ls_s,
    const float* __restrict__ eps_s,
    float* __restrict__ out_base, float* __restrict__ kl_out)
{
    __shared__ float sXT[CH * XPITCH];   // [k][r] transposed X tile
    __shared__ float sW[CH * CH];        // [k][c] weights (built here)
    __shared__ float sred[256];

    int branch = blockIdx.y;
    int row0 = blockIdx.x * 64;
    int tid = threadIdx.x;
    int bid = blockIdx.x + GX * branch;  // 0..1563

    // (a) zero 1024 float4 of the output accumulation area
    {
        float4* out4 = (float4*)out_base;
        float4 z = make_float4(0.f, 0.f, 0.f, 0.f);
        #pragma unroll
        for (int t = 0; t < 4; t++) {
            int i = bid * 1024 + t * 256 + tid;
            if (i < ZERO_FLOAT4) out4[i] = z;
        }
    }

    // (b) build W for this branch into sW
    {
        const float* mu  = branch ? mu_s  : mu_m;
        const float* ls  = branch ? ls_s  : ls_m;
        const float* eps = branch ? eps_s : eps_m;
        for (int i = tid; i < CH * CH; i += 256)
            sW[i] = mu[i] + eps[i] * expf(ls[i]);
    }

    // (c) KL: only block (0,0), both branches
    if (blockIdx.x == 0 && branch == 0) {
        float acc = 0.f;
        for (int i = tid; i < CH * CH; i += 256) {
            float lm = ls_m[i], mm = mu_m[i];
            acc += 0.5f * (expf(2.f * lm) + mm * mm - 2.f * lm - 1.f);
            float lv = ls_s[i], ms = mu_s[i];
            acc += 0.5f * (expf(2.f * lv) + ms * ms - 2.f * lv - 1.f);
        }
        sred[tid] = acc;
        __syncthreads();
        for (int s = 128; s > 0; s >>= 1) {
            if (tid < s) sred[tid] += sred[tid + s];
            __syncthreads();
        }
        if (tid == 0) kl_out[0] = sred[0];
    }

    // stage X tile transposed (64 rows x 16 float4)
    const float4* in4 = (const float4*)(branch ? stdv : mean);
    {
        int r = tid >> 4, c4 = tid & 15;   // 16 rows per pass, 4 passes
        #pragma unroll
        for (int p = 0; p < 4; p++) {
            int rr = p * 16 + r;
            int node = row0 + rr;
            float4 v = make_float4(0.f, 0.f, 0.f, 0.f);
            if (node < N_NODES) v = in4[node * CH4 + c4];
            if (branch) { v.x *= v.x; v.y *= v.y; v.z *= v.z; v.w *= v.w; }
            sXT[(c4 * 4 + 0) * XPITCH + rr] = v.x;
            sXT[(c4 * 4 + 1) * XPITCH + rr] = v.y;
            sXT[(c4 * 4 + 2) * XPITCH + rr] = v.z;
            sXT[(c4 * 4 + 3) * XPITCH + rr] = v.w;
        }
    }
    __syncthreads();

    // (d) 4x4 outputs per thread, f32x2 row-pair accumulators
    int tr = tid >> 4;   // 0..15 row group (4 rows)
    int tc = tid & 15;   // 0..15 col group (4 cols)

    unsigned long long acc[2][4] = {{0ull,0ull,0ull,0ull},{0ull,0ull,0ull,0ull}};

    #pragma unroll
    for (int k = 0; k < CH; k++) {
        float4 x = *(const float4*)&sXT[k * XPITCH + tr * 4];
        float4 w = *(const float4*)&sW [k * CH     + tc * 4];
        unsigned long long xp0, xp1;
        asm("mov.b64 %0, {%1, %2};" : "=l"(xp0) : "f"(x.x), "f"(x.y));
        asm("mov.b64 %0, {%1, %2};" : "=l"(xp1) : "f"(x.z), "f"(x.w));
        float wv[4] = {w.x, w.y, w.z, w.w};
        #pragma unroll
        for (int c = 0; c < 4; c++) {
            unsigned long long wp;
            asm("mov.b64 %0, {%1, %1};" : "=l"(wp) : "f"(wv[c]));
            asm("fma.rn.f32x2 %0, %1, %2, %0;" : "+l"(acc[0][c]) : "l"(xp0), "l"(wp));
            asm("fma.rn.f32x2 %0, %1, %2, %0;" : "+l"(acc[1][c]) : "l"(xp1), "l"(wp));
        }
    }

    float4* sup = g_sup[branch];
    #pragma unroll
    for (int p = 0; p < 2; p++) {
        float lo[4], hi[4];
        #pragma unroll
        for (int c = 0; c < 4; c++) {
            asm("mov.b64 {%0, %1}, %2;" : "=f"(lo[c]), "=f"(hi[c]) : "l"(acc[p][c]));
        }
        int n0 = row0 + tr * 4 + 2 * p;
        if (n0 < N_NODES)
            sup[n0 * CH4 + tc] = make_float4(lo[0], lo[1], lo[2], lo[3]);
        if (n0 + 1 < N_NODES)
            sup[(n0 + 1) * CH4 + tc] = make_float4(hi[0], hi[1], hi[2], hi[3]);
    }
}

// ---------------------------------------------------------------------------
// Kernel 2: edge scatter, both branches per thread.
// 16 consecutive lanes cover one edge's full 256B row per branch =>
// coalesced gathers; two red.global.add.v4 per thread (L2-bandwidth floor).
// ---------------------------------------------------------------------------
__global__ __launch_bounds__(256) void scatter_kernel(
    const int* __restrict__ ei, const float* __restrict__ ew,
    float* __restrict__ out_mean, float* __restrict__ out_var)
{
    int idx = blockIdx.x * 256 + threadIdx.x;          // < N_EDGES*16 = 12.8M
    int j = idx & 15;                                  // chunk within row
    int e = idx >> 4;                                  // edge

    int src = __ldg(&ei[e]);
    int dst = __ldg(&ei[N_EDGES + e]);
    float w = __ldg(&ew[e]);
    float q = w * w;

    float4 m = __ldg(&g_sup[0][src * CH4 + j]);
    float4 v = __ldg(&g_sup[1][src * CH4 + j]);

    float* am = out_mean + dst * CH + j * 4;
    float* av = out_var  + dst * CH + j * 4;
    asm volatile("red.global.add.v4.f32 [%0], {%1, %2, %3, %4};"
                 :: "l"(am), "f"(m.x * w), "f"(m.y * w), "f"(m.z * w), "f"(m.w * w)
                 : "memory");
    asm volatile("red.global.add.v4.f32 [%0], {%1, %2, %3, %4};"
                 :: "l"(av), "f"(v.x * q), "f"(v.y * q), "f"(v.z * q), "f"(v.w * q)
                 : "memory");
}

// ---------------------------------------------------------------------------
// Kernel 3: finalize std branch: std = sqrt(exp(log_var) + 1e-6), in place.
// ---------------------------------------------------------------------------
__global__ __launch_bounds__(256) void finalize_kernel(float4* __restrict__ out_var4) {
    int i = blockIdx.x * 256 + threadIdx.x;
    if (i < OUT_ELEMS / 4) {
        float4 x = out_var4[i];
        x.x = sqrtf(expf(x.x) + 1e-6f);
        x.y = sqrtf(expf(x.y) + 1e-6f);
        x.z = sqrtf(expf(x.z) + 1e-6f);
        x.w = sqrtf(expf(x.w) + 1e-6f);
        out_var4[i] = x;
    }
}

// ---------------------------------------------------------------------------
extern "C" void kernel_launch(void* const* d_in, const int* in_sizes, int n_in,
                              void* d_out, int out_size)
{
    const float* mean  = (const float*)d_in[0];   // [50000, 64]
    const float* stdv  = (const float*)d_in[1];   // [50000, 64]
    const int*   ei    = (const int*)  d_in[2];   // [2, 800000]
    const float* ew    = (const float*)d_in[3];   // [800000]
    const float* mu_m  = (const float*)d_in[4];
    const float* ls_m  = (const float*)d_in[5];
    const float* eps_m = (const float*)d_in[6];
    const float* mu_s  = (const float*)d_in[7];
    const float* ls_s  = (const float*)d_in[8];
    const float* eps_s = (const float*)d_in[9];

    float* out_mean = (float*)d_out;                   // [50000*64]
    float* out_var  = out_mean + OUT_ELEMS;            // [50000*64]
    float* kl_out   = out_mean + 2 * OUT_ELEMS;        // scalar

    // 1) fused: zero + weights + KL + dual GEMM
    {
        dim3 grid(GX, 2);
        gemm_fused_kernel<<<grid, 256>>>(mean, stdv,
                                         mu_m, ls_m, eps_m,
                                         mu_s, ls_s, eps_s,
                                         out_mean, kl_out);
    }
    // 2) edge scatter (both branches per thread)
    {
        int total = N_EDGES * 16;                      // 12,800,000
        scatter_kernel<<<total / 256, 256>>>(ei, ew, out_mean, out_var);
    }
    // 3) finalize std
    {
        int n4 = OUT_ELEMS / 4;
        finalize_kernel<<<(n4 + 255) / 256, 256>>>((float4*)out_var);
    }
}

// round 5
// speedup vs baseline: 1.6518x; 1.0243x over previous
#include <cuda_runtime.h>
#include <cstdint>

#define N_NODES 50000
#define N_EDGES 800000
#define CH 64
#define CH4 16
#define OUT_ELEMS (N_NODES * CH)
#define GX 782                       // ceil(50000/64)
#define ZERO_FLOAT4 (OUT_ELEMS * 2 / 4)   // 1,600,000

// ---- scratch (device globals; no allocation allowed) ----
__device__ float  g_w[2][CH * CH];            // reparameterized weights
__device__ float4 g_sup[2][N_NODES * CH4];    // support tensors as float4

// ---------------------------------------------------------------------------
// Kernel 1: wide prep — 16 blocks build W (512 elems each); block 0 also
// reduces the KL sum for both branches (parallel with the other blocks).
// ---------------------------------------------------------------------------
__global__ __launch_bounds__(256) void prep_kernel(
    const float* __restrict__ mu_m, const float* __restrict__ ls_m,
    const float* __restrict__ eps_m,
    const float* __restrict__ mu_s, const float* __restrict__ ls_s,
    const float* __restrict__ eps_s,
    float* __restrict__ kl_out)
{
    int tid = threadIdx.x;
    int base = blockIdx.x * 512;
    #pragma unroll
    for (int t = 0; t < 2; t++) {
        int i = base + t * 256 + tid;       // < 8192 (covers both branches)
        if (i < CH * CH) {
            g_w[0][i] = mu_m[i] + eps_m[i] * expf(ls_m[i]);
        } else {
            int j = i - CH * CH;
            g_w[1][j] = mu_s[j] + eps_s[j] * expf(ls_s[j]);
        }
    }

    if (blockIdx.x == 0) {
        __shared__ float sred[256];
        float acc = 0.f;
        for (int i = tid; i < CH * CH; i += 256) {
            float lm = ls_m[i], mm = mu_m[i];
            acc += 0.5f * (expf(2.f * lm) + mm * mm - 2.f * lm - 1.f);
            float lv = ls_s[i], ms = mu_s[i];
            acc += 0.5f * (expf(2.f * lv) + ms * ms - 2.f * lv - 1.f);
        }
        sred[tid] = acc;
        __syncthreads();
        for (int s = 128; s > 0; s >>= 1) {
            if (tid < s) sred[tid] += sred[tid + s];
            __syncthreads();
        }
        if (tid == 0) kl_out[0] = sred[0];
    }
}

// ---------------------------------------------------------------------------
// Kernel 2 (fused): per block —
//   (a) zero a slice of d_out accumulation area,
//   (b) stage this branch's W from global (built by prep),
//   (c) register-blocked 64x64 GEMM with packed f32x2 FMA.
//   branch 0: sup_mean = mean      @ W_mean
//   branch 1: sup_var  = (std*std) @ W_var
// ---------------------------------------------------------------------------
#define XPITCH 68
__global__ __launch_bounds__(256) void gemm_fused_kernel(
    const float* __restrict__ mean, const float* __restrict__ stdv,
    float* __restrict__ out_base)
{
    __shared__ float sXT[CH * XPITCH];   // [k][r] transposed X tile
    __shared__ float sW[CH * CH];        // [k][c] weights

    int branch = blockIdx.y;
    int row0 = blockIdx.x * 64;
    int tid = threadIdx.x;
    int bid = blockIdx.x + GX * branch;  // 0..1563

    // (a) zero 1024 float4 of the output accumulation area
    {
        float4* out4 = (float4*)out_base;
        float4 z = make_float4(0.f, 0.f, 0.f, 0.f);
        #pragma unroll
        for (int t = 0; t < 4; t++) {
            int i = bid * 1024 + t * 256 + tid;
            if (i < ZERO_FLOAT4) out4[i] = z;
        }
    }

    // (b) stage weights (1024 float4 from L2-resident g_w)
    {
        const float4* w4 = (const float4*)g_w[branch];
        for (int i = tid; i < CH * CH4; i += 256)
            ((float4*)sW)[i] = w4[i];
    }

    // stage X tile transposed (64 rows x 16 float4)
    const float4* in4 = (const float4*)(branch ? stdv : mean);
    {
        int r = tid >> 4, c4 = tid & 15;   // 16 rows per pass, 4 passes
        #pragma unroll
        for (int p = 0; p < 4; p++) {
            int rr = p * 16 + r;
            int node = row0 + rr;
            float4 v = make_float4(0.f, 0.f, 0.f, 0.f);
            if (node < N_NODES) v = in4[node * CH4 + c4];
            if (branch) { v.x *= v.x; v.y *= v.y; v.z *= v.z; v.w *= v.w; }
            sXT[(c4 * 4 + 0) * XPITCH + rr] = v.x;
            sXT[(c4 * 4 + 1) * XPITCH + rr] = v.y;
            sXT[(c4 * 4 + 2) * XPITCH + rr] = v.z;
            sXT[(c4 * 4 + 3) * XPITCH + rr] = v.w;
        }
    }
    __syncthreads();

    // (c) 4x4 outputs per thread, f32x2 row-pair accumulators
    int tr = tid >> 4;   // 0..15 row group (4 rows)
    int tc = tid & 15;   // 0..15 col group (4 cols)

    unsigned long long acc[2][4] = {{0ull,0ull,0ull,0ull},{0ull,0ull,0ull,0ull}};

    #pragma unroll
    for (int k = 0; k < CH; k++) {
        float4 x = *(const float4*)&sXT[k * XPITCH + tr * 4];
        float4 w = *(const float4*)&sW [k * CH     + tc * 4];
        unsigned long long xp0, xp1;
        asm("mov.b64 %0, {%1, %2};" : "=l"(xp0) : "f"(x.x), "f"(x.y));
        asm("mov.b64 %0, {%1, %2};" : "=l"(xp1) : "f"(x.z), "f"(x.w));
        float wv[4] = {w.x, w.y, w.z, w.w};
        #pragma unroll
        for (int c = 0; c < 4; c++) {
            unsigned long long wp;
            asm("mov.b64 %0, {%1, %1};" : "=l"(wp) : "f"(wv[c]));
            asm("fma.rn.f32x2 %0, %1, %2, %0;" : "+l"(acc[0][c]) : "l"(xp0), "l"(wp));
            asm("fma.rn.f32x2 %0, %1, %2, %0;" : "+l"(acc[1][c]) : "l"(xp1), "l"(wp));
        }
    }

    float4* sup = g_sup[branch];
    #pragma unroll
    for (int p = 0; p < 2; p++) {
        float lo[4], hi[4];
        #pragma unroll
        for (int c = 0; c < 4; c++) {
            asm("mov.b64 {%0, %1}, %2;" : "=f"(lo[c]), "=f"(hi[c]) : "l"(acc[p][c]));
        }
        int n0 = row0 + tr * 4 + 2 * p;
        if (n0 < N_NODES)
            sup[n0 * CH4 + tc] = make_float4(lo[0], lo[1], lo[2], lo[3]);
        if (n0 + 1 < N_NODES)
            sup[(n0 + 1) * CH4 + tc] = make_float4(hi[0], hi[1], hi[2], hi[3]);
    }
}

// ---------------------------------------------------------------------------
// Kernel 3: edge scatter, both branches per thread.
// 16 consecutive lanes cover one edge's full 256B row per branch =>
// coalesced gathers; two red.global.add.v4 per thread (L2-bandwidth floor).
// ---------------------------------------------------------------------------
__global__ __launch_bounds__(256) void scatter_kernel(
    const int* __restrict__ ei, const float* __restrict__ ew,
    float* __restrict__ out_mean, float* __restrict__ out_var)
{
    int idx = blockIdx.x * 256 + threadIdx.x;          // < N_EDGES*16 = 12.8M
    int j = idx & 15;                                  // chunk within row
    int e = idx >> 4;                                  // edge

    int src = __ldg(&ei[e]);
    int dst = __ldg(&ei[N_EDGES + e]);
    float w = __ldg(&ew[e]);
    float q = w * w;

    float4 m = __ldg(&g_sup[0][src * CH4 + j]);
    float4 v = __ldg(&g_sup[1][src * CH4 + j]);

    float* am = out_mean + dst * CH + j * 4;
    float* av = out_var  + dst * CH + j * 4;
    asm volatile("red.global.add.v4.f32 [%0], {%1, %2, %3, %4};"
                 :: "l"(am), "f"(m.x * w), "f"(m.y * w), "f"(m.z * w), "f"(m.w * w)
                 : "memory");
    asm volatile("red.global.add.v4.f32 [%0], {%1, %2, %3, %4};"
                 :: "l"(av), "f"(v.x * q), "f"(v.y * q), "f"(v.z * q), "f"(v.w * q)
                 : "memory");
}

// ---------------------------------------------------------------------------
// Kernel 4: finalize std branch: std = sqrt(exp(log_var) + 1e-6), in place.
// ---------------------------------------------------------------------------
__global__ __launch_bounds__(256) void finalize_kernel(float4* __restrict__ out_var4) {
    int i = blockIdx.x * 256 + threadIdx.x;
    if (i < OUT_ELEMS / 4) {
        float4 x = out_var4[i];
        x.x = sqrtf(expf(x.x) + 1e-6f);
        x.y = sqrtf(expf(x.y) + 1e-6f);
        x.z = sqrtf(expf(x.z) + 1e-6f);
        x.w = sqrtf(expf(x.w) + 1e-6f);
        out_var4[i] = x;
    }
}

// ---------------------------------------------------------------------------
extern "C" void kernel_launch(void* const* d_in, const int* in_sizes, int n_in,
                              void* d_out, int out_size)
{
    const float* mean  = (const float*)d_in[0];   // [50000, 64]
    const float* stdv  = (const float*)d_in[1];   // [50000, 64]
    const int*   ei    = (const int*)  d_in[2];   // [2, 800000]
    const float* ew    = (const float*)d_in[3];   // [800000]
    const float* mu_m  = (const float*)d_in[4];
    const float* ls_m  = (const float*)d_in[5];
    const float* eps_m = (const float*)d_in[6];
    const float* mu_s  = (const float*)d_in[7];
    const float* ls_s  = (const float*)d_in[8];
    const float* eps_s = (const float*)d_in[9];

    float* out_mean = (float*)d_out;                   // [50000*64]
    float* out_var  = out_mean + OUT_ELEMS;            // [50000*64]
    float* kl_out   = out_mean + 2 * OUT_ELEMS;        // scalar

    // 1) wide prep: weights + KL
    prep_kernel<<<16, 256>>>(mu_m, ls_m, eps_m, mu_s, ls_s, eps_s, kl_out);
    // 2) fused: zero + dual GEMM
    {
        dim3 grid(GX, 2);
        gemm_fused_kernel<<<grid, 256>>>(mean, stdv, out_mean);
    }
    // 3) edge scatter (both branches per thread)
    {
        int total = N_EDGES * 16;                      // 12,800,000
        scatter_kernel<<<total / 256, 256>>>(ei, ew, out_mean, out_var);
    }
    // 4) finalize std
    {
        int n4 = OUT_ELEMS / 4;
        finalize_kernel<<<(n4 + 255) / 256, 256>>>((float4*)out_var);
    }
}

// round 6
// speedup vs baseline: 1.6895x; 1.0228x over previous
#include <cuda_runtime.h>
#include <cstdint>

#define N_NODES 50000
#define N_EDGES 800000
#define CH 64
#define CH4 16
#define OUT_ELEMS (N_NODES * CH)
#define GX 391                            // ceil(50000/128)
#define ZERO_FLOAT4 (OUT_ELEMS * 2 / 4)   // 1,600,000

// ---- scratch (device globals; no allocation allowed) ----
__device__ float  g_w[2][CH * CH];            // reparameterized weights
__device__ float4 g_sup[2][N_NODES * CH4];    // support tensors as float4

// ---------------------------------------------------------------------------
// Kernel 1: prep + zero. 400 blocks:
//   all blocks: zero a 4096-float4 slice of the output accumulation area
//   blocks 0..15: build W (512 elems each)
//   block 0: reduce KL for both branches
// ---------------------------------------------------------------------------
__global__ __launch_bounds__(256) void prep_zero_kernel(
    const float* __restrict__ mu_m, const float* __restrict__ ls_m,
    const float* __restrict__ eps_m,
    const float* __restrict__ mu_s, const float* __restrict__ ls_s,
    const float* __restrict__ eps_s,
    float* __restrict__ out_base, float* __restrict__ kl_out)
{
    int tid = threadIdx.x;
    int bid = blockIdx.x;

    // zero slice
    {
        float4* out4 = (float4*)out_base;
        float4 z = make_float4(0.f, 0.f, 0.f, 0.f);
        #pragma unroll
        for (int t = 0; t < 16; t++) {
            int i = bid * 4096 + t * 256 + tid;
            if (i < ZERO_FLOAT4) out4[i] = z;
        }
    }

    // W build (blocks 0..15)
    if (bid < 16) {
        int base = bid * 512;
        #pragma unroll
        for (int t = 0; t < 2; t++) {
            int i = base + t * 256 + tid;       // < 8192 covers both branches
            if (i < CH * CH) {
                g_w[0][i] = mu_m[i] + eps_m[i] * expf(ls_m[i]);
            } else {
                int j = i - CH * CH;
                g_w[1][j] = mu_s[j] + eps_s[j] * expf(ls_s[j]);
            }
        }
    }

    // KL (block 0)
    if (bid == 0) {
        __shared__ float sred[256];
        float acc = 0.f;
        for (int i = tid; i < CH * CH; i += 256) {
            float lm = ls_m[i], mm = mu_m[i];
            acc += 0.5f * (expf(2.f * lm) + mm * mm - 2.f * lm - 1.f);
            float lv = ls_s[i], ms = mu_s[i];
            acc += 0.5f * (expf(2.f * lv) + ms * ms - 2.f * lv - 1.f);
        }
        sred[tid] = acc;
        __syncthreads();
        for (int s = 128; s > 0; s >>= 1) {
            if (tid < s) sred[tid] += sred[tid + s];
            __syncthreads();
        }
        if (tid == 0) kl_out[0] = sred[0];
    }
}

// ---------------------------------------------------------------------------
// Kernel 2: register-blocked GEMM, 128x64 tile, 8 rows x 4 cols per thread,
// packed f32x2 FMA. branch 0: mean @ W_mean; branch 1: (std*std) @ W_var.
// ---------------------------------------------------------------------------
#define XPITCH 132
__global__ __launch_bounds__(256) void gemm_kernel(
    const float* __restrict__ mean, const float* __restrict__ stdv)
{
    __shared__ float sXT[CH * XPITCH];   // [k][row] transposed X tile (128 rows)
    __shared__ float sW[CH * CH];        // [k][c]

    int branch = blockIdx.y;
    int row0 = blockIdx.x * 128;
    int tid = threadIdx.x;

    // stage weights (1024 float4 from L2-resident g_w)
    {
        const float4* w4 = (const float4*)g_w[branch];
        for (int i = tid; i < CH * CH4; i += 256)
            ((float4*)sW)[i] = w4[i];
    }

    // stage X tile transposed: 128 rows x 16 float4 chunks = 2048 loads.
    // idx mapping row = idx&127 -> consecutive tids hit consecutive rows
    // (conflict-free smem writes).
    const float4* in4 = (const float4*)(branch ? stdv : mean);
    {
        #pragma unroll
        for (int p = 0; p < 8; p++) {
            int idx = p * 256 + tid;
            int row = idx & 127;
            int c4 = idx >> 7;
            int node = row0 + row;
            float4 v = make_float4(0.f, 0.f, 0.f, 0.f);
            if (node < N_NODES) v = in4[node * CH4 + c4];
            if (branch) { v.x *= v.x; v.y *= v.y; v.z *= v.z; v.w *= v.w; }
            sXT[(c4 * 4 + 0) * XPITCH + row] = v.x;
            sXT[(c4 * 4 + 1) * XPITCH + row] = v.y;
            sXT[(c4 * 4 + 2) * XPITCH + row] = v.z;
            sXT[(c4 * 4 + 3) * XPITCH + row] = v.w;
        }
    }
    __syncthreads();

    int tr = tid >> 4;   // 0..15 -> rows tr*8 .. tr*8+7
    int tc = tid & 15;   // 0..15 -> cols tc*4 .. tc*4+3

    // acc[p][c]: row pair (tr*8+2p, tr*8+2p+1), col tc*4+c
    unsigned long long acc[4][4];
    #pragma unroll
    for (int p = 0; p < 4; p++)
        #pragma unroll
        for (int c = 0; c < 4; c++) acc[p][c] = 0ull;

    #pragma unroll
    for (int k = 0; k < CH; k++) {
        float4 xa = *(const float4*)&sXT[k * XPITCH + tr * 8];
        float4 xb = *(const float4*)&sXT[k * XPITCH + tr * 8 + 4];
        float4 w  = *(const float4*)&sW [k * CH     + tc * 4];
        unsigned long long xp[4];
        asm("mov.b64 %0, {%1, %2};" : "=l"(xp[0]) : "f"(xa.x), "f"(xa.y));
        asm("mov.b64 %0, {%1, %2};" : "=l"(xp[1]) : "f"(xa.z), "f"(xa.w));
        asm("mov.b64 %0, {%1, %2};" : "=l"(xp[2]) : "f"(xb.x), "f"(xb.y));
        asm("mov.b64 %0, {%1, %2};" : "=l"(xp[3]) : "f"(xb.z), "f"(xb.w));
        float wv[4] = {w.x, w.y, w.z, w.w};
        #pragma unroll
        for (int c = 0; c < 4; c++) {
            unsigned long long wp;
            asm("mov.b64 %0, {%1, %1};" : "=l"(wp) : "f"(wv[c]));
            #pragma unroll
            for (int p = 0; p < 4; p++) {
                asm("fma.rn.f32x2 %0, %1, %2, %0;"
                    : "+l"(acc[p][c]) : "l"(xp[p]), "l"(wp));
            }
        }
    }

    float4* sup = g_sup[branch];
    #pragma unroll
    for (int p = 0; p < 4; p++) {
        float lo[4], hi[4];
        #pragma unroll
        for (int c = 0; c < 4; c++) {
            asm("mov.b64 {%0, %1}, %2;" : "=f"(lo[c]), "=f"(hi[c]) : "l"(acc[p][c]));
        }
        int n0 = row0 + tr * 8 + 2 * p;
        if (n0 < N_NODES)
            sup[n0 * CH4 + tc] = make_float4(lo[0], lo[1], lo[2], lo[3]);
        if (n0 + 1 < N_NODES)
            sup[(n0 + 1) * CH4 + tc] = make_float4(hi[0], hi[1], hi[2], hi[3]);
    }
}

// ---------------------------------------------------------------------------
// Kernel 3: edge scatter, both branches per thread (L2-bandwidth floor).
// ---------------------------------------------------------------------------
__global__ __launch_bounds__(256) void scatter_kernel(
    const int* __restrict__ ei, const float* __restrict__ ew,
    float* __restrict__ out_mean, float* __restrict__ out_var)
{
    int idx = blockIdx.x * 256 + threadIdx.x;          // < N_EDGES*16 = 12.8M
    int j = idx & 15;                                  // chunk within row
    int e = idx >> 4;                                  // edge

    int src = __ldg(&ei[e]);
    int dst = __ldg(&ei[N_EDGES + e]);
    float w = __ldg(&ew[e]);
    float q = w * w;

    float4 m = __ldg(&g_sup[0][src * CH4 + j]);
    float4 v = __ldg(&g_sup[1][src * CH4 + j]);

    float* am = out_mean + dst * CH + j * 4;
    float* av = out_var  + dst * CH + j * 4;
    asm volatile("red.global.add.v4.f32 [%0], {%1, %2, %3, %4};"
                 :: "l"(am), "f"(m.x * w), "f"(m.y * w), "f"(m.z * w), "f"(m.w * w)
                 : "memory");
    asm volatile("red.global.add.v4.f32 [%0], {%1, %2, %3, %4};"
                 :: "l"(av), "f"(v.x * q), "f"(v.y * q), "f"(v.z * q), "f"(v.w * q)
                 : "memory");
}

// ---------------------------------------------------------------------------
// Kernel 4: finalize std branch: std = sqrt(exp(log_var) + 1e-6), 4 f4/thread.
// ---------------------------------------------------------------------------
__global__ __launch_bounds__(256) void finalize_kernel(float4* __restrict__ out_var4) {
    int base = blockIdx.x * 1024 + threadIdx.x;
    #pragma unroll
    for (int t = 0; t < 4; t++) {
        int i = base + t * 256;
        if (i < OUT_ELEMS / 4) {
            float4 x = out_var4[i];
            x.x = sqrtf(expf(x.x) + 1e-6f);
            x.y = sqrtf(expf(x.y) + 1e-6f);
            x.z = sqrtf(expf(x.z) + 1e-6f);
            x.w = sqrtf(expf(x.w) + 1e-6f);
            out_var4[i] = x;
        }
    }
}

// ---------------------------------------------------------------------------
extern "C" void kernel_launch(void* const* d_in, const int* in_sizes, int n_in,
                              void* d_out, int out_size)
{
    const float* mean  = (const float*)d_in[0];   // [50000, 64]
    const float* stdv  = (const float*)d_in[1];   // [50000, 64]
    const int*   ei    = (const int*)  d_in[2];   // [2, 800000]
    const float* ew    = (const float*)d_in[3];   // [800000]
    const float* mu_m  = (const float*)d_in[4];
    const float* ls_m  = (const float*)d_in[5];
    const float* eps_m = (const float*)d_in[6];
    const float* mu_s  = (const float*)d_in[7];
    const float* ls_s  = (const float*)d_in[8];
    const float* eps_s = (const float*)d_in[9];

    float* out_mean = (float*)d_out;                   // [50000*64]
    float* out_var  = out_mean + OUT_ELEMS;            // [50000*64]
    float* kl_out   = out_mean + 2 * OUT_ELEMS;        // scalar

    // 1) prep + zero: weights + KL + clear accumulators
    prep_zero_kernel<<<400, 256>>>(mu_m, ls_m, eps_m, mu_s, ls_s, eps_s,
                                   out_mean, kl_out);
    // 2) dual GEMM -> support tensors
    {
        dim3 grid(GX, 2);
        gemm_kernel<<<grid, 256>>>(mean, stdv);
    }
    // 3) edge scatter (both branches per thread)
    {
        int total = N_EDGES * 16;                      // 12,800,000
        scatter_kernel<<<total / 256, 256>>>(ei, ew, out_mean, out_var);
    }
    // 4) finalize std
    finalize_kernel<<<782, 256>>>((float4*)out_var);
}

// round 7
// speedup vs baseline: 1.7371x; 1.0282x over previous
#include <cuda_runtime.h>
#include <cstdint>

#define N_NODES 50000
#define N_EDGES 800000
#define HALF_E (N_EDGES / 2)
#define CH 64
#define CH4 16
#define OUT_ELEMS (N_NODES * CH)
#define GX 391                            // ceil(50000/128)
#define ZERO_FLOAT4 (OUT_ELEMS * 2 / 4)   // 1,600,000

// ---- scratch (device globals; no allocation allowed) ----
__device__ float  g_w[2][CH * CH];            // reparameterized weights
__device__ float4 g_sup[2][N_NODES * CH4];    // support tensors as float4

// ---------------------------------------------------------------------------
// Kernel 1: prep + zero. 400 blocks:
//   all blocks: zero a 4096-float4 slice of the output accumulation area
//   blocks 0..15: build W (512 elems each)
//   block 0: reduce KL for both branches
// ---------------------------------------------------------------------------
__global__ __launch_bounds__(256) void prep_zero_kernel(
    const float* __restrict__ mu_m, const float* __restrict__ ls_m,
    const float* __restrict__ eps_m,
    const float* __restrict__ mu_s, const float* __restrict__ ls_s,
    const float* __restrict__ eps_s,
    float* __restrict__ out_base, float* __restrict__ kl_out)
{
    int tid = threadIdx.x;
    int bid = blockIdx.x;

    // zero slice
    {
        float4* out4 = (float4*)out_base;
        float4 z = make_float4(0.f, 0.f, 0.f, 0.f);
        #pragma unroll
        for (int t = 0; t < 16; t++) {
            int i = bid * 4096 + t * 256 + tid;
            if (i < ZERO_FLOAT4) out4[i] = z;
        }
    }

    // W build (blocks 0..15)
    if (bid < 16) {
        int base = bid * 512;
        #pragma unroll
        for (int t = 0; t < 2; t++) {
            int i = base + t * 256 + tid;       // < 8192 covers both branches
            if (i < CH * CH) {
                g_w[0][i] = mu_m[i] + eps_m[i] * expf(ls_m[i]);
            } else {
                int j = i - CH * CH;
                g_w[1][j] = mu_s[j] + eps_s[j] * expf(ls_s[j]);
            }
        }
    }

    // KL (block 0)
    if (bid == 0) {
        __shared__ float sred[256];
        float acc = 0.f;
        for (int i = tid; i < CH * CH; i += 256) {
            float lm = ls_m[i], mm = mu_m[i];
            acc += 0.5f * (expf(2.f * lm) + mm * mm - 2.f * lm - 1.f);
            float lv = ls_s[i], ms = mu_s[i];
            acc += 0.5f * (expf(2.f * lv) + ms * ms - 2.f * lv - 1.f);
        }
        sred[tid] = acc;
        __syncthreads();
        for (int s = 128; s > 0; s >>= 1) {
            if (tid < s) sred[tid] += sred[tid + s];
            __syncthreads();
        }
        if (tid == 0) kl_out[0] = sred[0];
    }
}

// ---------------------------------------------------------------------------
// Kernel 2: register-blocked GEMM, 128x64 tile, 8 rows x 4 cols per thread,
// packed f32x2 FMA. branch 0: mean @ W_mean; branch 1: (std*std) @ W_var.
// ---------------------------------------------------------------------------
#define XPITCH 132
__global__ __launch_bounds__(256) void gemm_kernel(
    const float* __restrict__ mean, const float* __restrict__ stdv)
{
    __shared__ float sXT[CH * XPITCH];   // [k][row] transposed X tile (128 rows)
    __shared__ float sW[CH * CH];        // [k][c]

    int branch = blockIdx.y;
    int row0 = blockIdx.x * 128;
    int tid = threadIdx.x;

    // stage weights (1024 float4 from L2-resident g_w)
    {
        const float4* w4 = (const float4*)g_w[branch];
        for (int i = tid; i < CH * CH4; i += 256)
            ((float4*)sW)[i] = w4[i];
    }

    // stage X tile transposed: 128 rows x 16 float4 chunks
    const float4* in4 = (const float4*)(branch ? stdv : mean);
    {
        #pragma unroll
        for (int p = 0; p < 8; p++) {
            int idx = p * 256 + tid;
            int row = idx & 127;
            int c4 = idx >> 7;
            int node = row0 + row;
            float4 v = make_float4(0.f, 0.f, 0.f, 0.f);
            if (node < N_NODES) v = in4[node * CH4 + c4];
            if (branch) { v.x *= v.x; v.y *= v.y; v.z *= v.z; v.w *= v.w; }
            sXT[(c4 * 4 + 0) * XPITCH + row] = v.x;
            sXT[(c4 * 4 + 1) * XPITCH + row] = v.y;
            sXT[(c4 * 4 + 2) * XPITCH + row] = v.z;
            sXT[(c4 * 4 + 3) * XPITCH + row] = v.w;
        }
    }
    __syncthreads();

    int tr = tid >> 4;   // 0..15 -> rows tr*8 .. tr*8+7
    int tc = tid & 15;   // 0..15 -> cols tc*4 .. tc*4+3

    unsigned long long acc[4][4];
    #pragma unroll
    for (int p = 0; p < 4; p++)
        #pragma unroll
        for (int c = 0; c < 4; c++) acc[p][c] = 0ull;

    #pragma unroll
    for (int k = 0; k < CH; k++) {
        float4 xa = *(const float4*)&sXT[k * XPITCH + tr * 8];
        float4 xb = *(const float4*)&sXT[k * XPITCH + tr * 8 + 4];
        float4 w  = *(const float4*)&sW [k * CH     + tc * 4];
        unsigned long long xp[4];
        asm("mov.b64 %0, {%1, %2};" : "=l"(xp[0]) : "f"(xa.x), "f"(xa.y));
        asm("mov.b64 %0, {%1, %2};" : "=l"(xp[1]) : "f"(xa.z), "f"(xa.w));
        asm("mov.b64 %0, {%1, %2};" : "=l"(xp[2]) : "f"(xb.x), "f"(xb.y));
        asm("mov.b64 %0, {%1, %2};" : "=l"(xp[3]) : "f"(xb.z), "f"(xb.w));
        float wv[4] = {w.x, w.y, w.z, w.w};
        #pragma unroll
        for (int c = 0; c < 4; c++) {
            unsigned long long wp;
            asm("mov.b64 %0, {%1, %1};" : "=l"(wp) : "f"(wv[c]));
            #pragma unroll
            for (int p = 0; p < 4; p++) {
                asm("fma.rn.f32x2 %0, %1, %2, %0;"
                    : "+l"(acc[p][c]) : "l"(xp[p]), "l"(wp));
            }
        }
    }

    float4* sup = g_sup[branch];
    #pragma unroll
    for (int p = 0; p < 4; p++) {
        float lo[4], hi[4];
        #pragma unroll
        for (int c = 0; c < 4; c++) {
            asm("mov.b64 {%0, %1}, %2;" : "=f"(lo[c]), "=f"(hi[c]) : "l"(acc[p][c]));
        }
        int n0 = row0 + tr * 8 + 2 * p;
        if (n0 < N_NODES)
            sup[n0 * CH4 + tc] = make_float4(lo[0], lo[1], lo[2], lo[3]);
        if (n0 + 1 < N_NODES)
            sup[(n0 + 1) * CH4 + tc] = make_float4(hi[0], hi[1], hi[2], hi[3]);
    }
}

// ---------------------------------------------------------------------------
// Kernel 3: edge scatter, TWO edges + both branches per thread.
// All meta loads front-batched, then 4 gathers, then 4 red.v4 — doubles
// outstanding loads per warp (raise MLP -> push L2 toward its cap).
// ---------------------------------------------------------------------------
__global__ __launch_bounds__(512) void scatter_kernel(
    const int* __restrict__ ei, const float* __restrict__ ew,
    float* __restrict__ out_mean, float* __restrict__ out_var)
{
    int idx = blockIdx.x * 512 + threadIdx.x;          // < HALF_E*16 = 6.4M
    int j = idx & 15;                                  // chunk within row
    int e0 = idx >> 4;                                 // 0..HALF_E-1
    int e1 = e0 + HALF_E;

    // front-batched meta loads (6 independent)
    int   s0 = __ldg(&ei[e0]);
    int   s1 = __ldg(&ei[e1]);
    int   d0 = __ldg(&ei[N_EDGES + e0]);
    int   d1 = __ldg(&ei[N_EDGES + e1]);
    float w0 = __ldg(&ew[e0]);
    float w1 = __ldg(&ew[e1]);

    // 4 independent gathers
    float4 m0 = __ldg(&g_sup[0][s0 * CH4 + j]);
    float4 m1 = __ldg(&g_sup[0][s1 * CH4 + j]);
    float4 v0 = __ldg(&g_sup[1][s0 * CH4 + j]);
    float4 v1 = __ldg(&g_sup[1][s1 * CH4 + j]);

    float q0 = w0 * w0, q1 = w1 * w1;

    float* am0 = out_mean + d0 * CH + j * 4;
    float* av0 = out_var  + d0 * CH + j * 4;
    float* am1 = out_mean + d1 * CH + j * 4;
    float* av1 = out_var  + d1 * CH + j * 4;

    asm volatile("red.global.add.v4.f32 [%0], {%1, %2, %3, %4};"
                 :: "l"(am0), "f"(m0.x * w0), "f"(m0.y * w0), "f"(m0.z * w0), "f"(m0.w * w0)
                 : "memory");
    asm volatile("red.global.add.v4.f32 [%0], {%1, %2, %3, %4};"
                 :: "l"(av0), "f"(v0.x * q0), "f"(v0.y * q0), "f"(v0.z * q0), "f"(v0.w * q0)
                 : "memory");
    asm volatile("red.global.add.v4.f32 [%0], {%1, %2, %3, %4};"
                 :: "l"(am1), "f"(m1.x * w1), "f"(m1.y * w1), "f"(m1.z * w1), "f"(m1.w * w1)
                 : "memory");
    asm volatile("red.global.add.v4.f32 [%0], {%1, %2, %3, %4};"
                 :: "l"(av1), "f"(v1.x * q1), "f"(v1.y * q1), "f"(v1.z * q1), "f"(v1.w * q1)
                 : "memory");
}

// ---------------------------------------------------------------------------
// Kernel 4: finalize std branch: std = sqrt(exp(log_var) + 1e-6), 4 f4/thread.
// ---------------------------------------------------------------------------
__global__ __launch_bounds__(256) void finalize_kernel(float4* __restrict__ out_var4) {
    int base = blockIdx.x * 1024 + threadIdx.x;
    #pragma unroll
    for (int t = 0; t < 4; t++) {
        int i = base + t * 256;
        if (i < OUT_ELEMS / 4) {
            float4 x = out_var4[i];
            x.x = sqrtf(expf(x.x) + 1e-6f);
            x.y = sqrtf(expf(x.y) + 1e-6f);
            x.z = sqrtf(expf(x.z) + 1e-6f);
            x.w = sqrtf(expf(x.w) + 1e-6f);
            out_var4[i] = x;
        }
    }
}

// ---------------------------------------------------------------------------
extern "C" void kernel_launch(void* const* d_in, const int* in_sizes, int n_in,
                              void* d_out, int out_size)
{
    const float* mean  = (const float*)d_in[0];   // [50000, 64]
    const float* stdv  = (const float*)d_in[1];   // [50000, 64]
    const int*   ei    = (const int*)  d_in[2];   // [2, 800000]
    const float* ew    = (const float*)d_in[3];   // [800000]
    const float* mu_m  = (const float*)d_in[4];
    const float* ls_m  = (const float*)d_in[5];
    const float* eps_m = (const float*)d_in[6];
    const float* mu_s  = (const float*)d_in[7];
    const float* ls_s  = (const float*)d_in[8];
    const float* eps_s = (const float*)d_in[9];

    float* out_mean = (float*)d_out;                   // [50000*64]
    float* out_var  = out_mean + OUT_ELEMS;            // [50000*64]
    float* kl_out   = out_mean + 2 * OUT_ELEMS;        // scalar

    // 1) prep + zero: weights + KL + clear accumulators
    prep_zero_kernel<<<400, 256>>>(mu_m, ls_m, eps_m, mu_s, ls_s, eps_s,
                                   out_mean, kl_out);
    // 2) dual GEMM -> support tensors
    {
        dim3 grid(GX, 2);
        gemm_kernel<<<grid, 256>>>(mean, stdv);
    }
    // 3) edge scatter (2 edges x both branches per thread)
    {
        int total = HALF_E * 16;                       // 6,400,000 threads
        scatter_kernel<<<total / 512, 512>>>(ei, ew, out_mean, out_var);
    }
    // 4) finalize std
    finalize_kernel<<<782, 256>>>((float4*)out_var);
}

// round 8
// speedup vs baseline: 1.8488x; 1.0643x over previous
#include <cuda_runtime.h>
#include <cuda_fp16.h>
#include <cstdint>

#define N_NODES 50000
#define N_EDGES 800000
#define HALF_E (N_EDGES / 2)
#define CH 64
#define CH4 16
#define OUT_ELEMS (N_NODES * CH)
#define GX 391                            // ceil(50000/128)
#define ZERO_FLOAT4 (OUT_ELEMS * 2 / 4)   // 1,600,000

// ---- scratch (device globals; no allocation allowed) ----
__device__ float g_w[2][CH * CH];             // reparameterized weights
// support tensors in fp16: [branch][node*16 + chunk], chunk = 4 halves (8B)
__device__ uint2 g_suph[2][N_NODES * CH4];

// ---------------------------------------------------------------------------
// Kernel 1: prep + zero. 400 blocks:
//   all blocks: zero a 4096-float4 slice of the output accumulation area
//   blocks 0..15: build W (512 elems each)
//   block 0: reduce KL for both branches
// ---------------------------------------------------------------------------
__global__ __launch_bounds__(256) void prep_zero_kernel(
    const float* __restrict__ mu_m, const float* __restrict__ ls_m,
    const float* __restrict__ eps_m,
    const float* __restrict__ mu_s, const float* __restrict__ ls_s,
    const float* __restrict__ eps_s,
    float* __restrict__ out_base, float* __restrict__ kl_out)
{
    int tid = threadIdx.x;
    int bid = blockIdx.x;

    // zero slice
    {
        float4* out4 = (float4*)out_base;
        float4 z = make_float4(0.f, 0.f, 0.f, 0.f);
        #pragma unroll
        for (int t = 0; t < 16; t++) {
            int i = bid * 4096 + t * 256 + tid;
            if (i < ZERO_FLOAT4) out4[i] = z;
        }
    }

    // W build (blocks 0..15)
    if (bid < 16) {
        int base = bid * 512;
        #pragma unroll
        for (int t = 0; t < 2; t++) {
            int i = base + t * 256 + tid;       // < 8192 covers both branches
            if (i < CH * CH) {
                g_w[0][i] = mu_m[i] + eps_m[i] * expf(ls_m[i]);
            } else {
                int j = i - CH * CH;
                g_w[1][j] = mu_s[j] + eps_s[j] * expf(ls_s[j]);
            }
        }
    }

    // KL (block 0)
    if (bid == 0) {
        __shared__ float sred[256];
        float acc = 0.f;
        for (int i = tid; i < CH * CH; i += 256) {
            float lm = ls_m[i], mm = mu_m[i];
            acc += 0.5f * (expf(2.f * lm) + mm * mm - 2.f * lm - 1.f);
            float lv = ls_s[i], ms = mu_s[i];
            acc += 0.5f * (expf(2.f * lv) + ms * ms - 2.f * lv - 1.f);
        }
        sred[tid] = acc;
        __syncthreads();
        for (int s = 128; s > 0; s >>= 1) {
            if (tid < s) sred[tid] += sred[tid + s];
            __syncthreads();
        }
        if (tid == 0) kl_out[0] = sred[0];
    }
}

// ---------------------------------------------------------------------------
// Kernel 2: register-blocked GEMM, 128x64 tile, 8 rows x 4 cols per thread,
// packed f32x2 FMA; epilogue converts to fp16 support tensors.
// ---------------------------------------------------------------------------
#define XPITCH 132
__global__ __launch_bounds__(256) void gemm_kernel(
    const float* __restrict__ mean, const float* __restrict__ stdv)
{
    __shared__ float sXT[CH * XPITCH];   // [k][row] transposed X tile (128 rows)
    __shared__ float sW[CH * CH];        // [k][c]

    int branch = blockIdx.y;
    int row0 = blockIdx.x * 128;
    int tid = threadIdx.x;

    // stage weights (1024 float4 from L2-resident g_w)
    {
        const float4* w4 = (const float4*)g_w[branch];
        for (int i = tid; i < CH * CH4; i += 256)
            ((float4*)sW)[i] = w4[i];
    }

    // stage X tile transposed: 128 rows x 16 float4 chunks
    const float4* in4 = (const float4*)(branch ? stdv : mean);
    {
        #pragma unroll
        for (int p = 0; p < 8; p++) {
            int idx = p * 256 + tid;
            int row = idx & 127;
            int c4 = idx >> 7;
            int node = row0 + row;
            float4 v = make_float4(0.f, 0.f, 0.f, 0.f);
            if (node < N_NODES) v = in4[node * CH4 + c4];
            if (branch) { v.x *= v.x; v.y *= v.y; v.z *= v.z; v.w *= v.w; }
            sXT[(c4 * 4 + 0) * XPITCH + row] = v.x;
            sXT[(c4 * 4 + 1) * XPITCH + row] = v.y;
            sXT[(c4 * 4 + 2) * XPITCH + row] = v.z;
            sXT[(c4 * 4 + 3) * XPITCH + row] = v.w;
        }
    }
    __syncthreads();

    int tr = tid >> 4;   // 0..15 -> rows tr*8 .. tr*8+7
    int tc = tid & 15;   // 0..15 -> cols tc*4 .. tc*4+3

    unsigned long long acc[4][4];
    #pragma unroll
    for (int p = 0; p < 4; p++)
        #pragma unroll
        for (int c = 0; c < 4; c++) acc[p][c] = 0ull;

    #pragma unroll
    for (int k = 0; k < CH; k++) {
        float4 xa = *(const float4*)&sXT[k * XPITCH + tr * 8];
        float4 xb = *(const float4*)&sXT[k * XPITCH + tr * 8 + 4];
        float4 w  = *(const float4*)&sW [k * CH     + tc * 4];
        unsigned long long xp[4];
        asm("mov.b64 %0, {%1, %2};" : "=l"(xp[0]) : "f"(xa.x), "f"(xa.y));
        asm("mov.b64 %0, {%1, %2};" : "=l"(xp[1]) : "f"(xa.z), "f"(xa.w));
        asm("mov.b64 %0, {%1, %2};" : "=l"(xp[2]) : "f"(xb.x), "f"(xb.y));
        asm("mov.b64 %0, {%1, %2};" : "=l"(xp[3]) : "f"(xb.z), "f"(xb.w));
        float wv[4] = {w.x, w.y, w.z, w.w};
        #pragma unroll
        for (int c = 0; c < 4; c++) {
            unsigned long long wp;
            asm("mov.b64 %0, {%1, %1};" : "=l"(wp) : "f"(wv[c]));
            #pragma unroll
            for (int p = 0; p < 4; p++) {
                asm("fma.rn.f32x2 %0, %1, %2, %0;"
                    : "+l"(acc[p][c]) : "l"(xp[p]), "l"(wp));
            }
        }
    }

    uint2* sup = g_suph[branch];
    #pragma unroll
    for (int p = 0; p < 4; p++) {
        float lo[4], hi[4];
        #pragma unroll
        for (int c = 0; c < 4; c++) {
            asm("mov.b64 {%0, %1}, %2;" : "=f"(lo[c]), "=f"(hi[c]) : "l"(acc[p][c]));
        }
        int n0 = row0 + tr * 8 + 2 * p;
        if (n0 < N_NODES) {
            __half2 h0 = __floats2half2_rn(lo[0], lo[1]);
            __half2 h1 = __floats2half2_rn(lo[2], lo[3]);
            sup[n0 * CH4 + tc] = make_uint2(*(unsigned*)&h0, *(unsigned*)&h1);
        }
        if (n0 + 1 < N_NODES) {
            __half2 h0 = __floats2half2_rn(hi[0], hi[1]);
            __half2 h1 = __floats2half2_rn(hi[2], hi[3]);
            sup[(n0 + 1) * CH4 + tc] = make_uint2(*(unsigned*)&h0, *(unsigned*)&h1);
        }
    }
}

// ---------------------------------------------------------------------------
// Kernel 3: edge scatter, TWO edges + both branches per thread.
// fp16 gathers (half the L2 gather bytes), fp32 vector reductions out.
// 16 lanes cover one edge's 128B fp16 row; red.v4 targets the 256B fp32 row.
// ---------------------------------------------------------------------------
__global__ __launch_bounds__(512) void scatter_kernel(
    const int* __restrict__ ei, const float* __restrict__ ew,
    float* __restrict__ out_mean, float* __restrict__ out_var)
{
    int idx = blockIdx.x * 512 + threadIdx.x;          // < HALF_E*16 = 6.4M
    int j = idx & 15;                                  // chunk within row
    int e0 = idx >> 4;                                 // 0..HALF_E-1
    int e1 = e0 + HALF_E;

    // front-batched meta loads (6 independent)
    int   s0 = __ldg(&ei[e0]);
    int   s1 = __ldg(&ei[e1]);
    int   d0 = __ldg(&ei[N_EDGES + e0]);
    int   d1 = __ldg(&ei[N_EDGES + e1]);
    float w0 = __ldg(&ew[e0]);
    float w1 = __ldg(&ew[e1]);

    // 4 independent fp16 gathers (8B each; warp-coalesced 128B rows)
    uint2 m0h = __ldg(&g_suph[0][s0 * CH4 + j]);
    uint2 m1h = __ldg(&g_suph[0][s1 * CH4 + j]);
    uint2 v0h = __ldg(&g_suph[1][s0 * CH4 + j]);
    uint2 v1h = __ldg(&g_suph[1][s1 * CH4 + j]);

    float q0 = w0 * w0, q1 = w1 * w1;

    float2 m0a = __half22float2(*(__half2*)&m0h.x);
    float2 m0b = __half22float2(*(__half2*)&m0h.y);
    float2 m1a = __half22float2(*(__half2*)&m1h.x);
    float2 m1b = __half22float2(*(__half2*)&m1h.y);
    float2 v0a = __half22float2(*(__half2*)&v0h.x);
    float2 v0b = __half22float2(*(__half2*)&v0h.y);
    float2 v1a = __half22float2(*(__half2*)&v1h.x);
    float2 v1b = __half22float2(*(__half2*)&v1h.y);

    float* am0 = out_mean + d0 * CH + j * 4;
    float* av0 = out_var  + d0 * CH + j * 4;
    float* am1 = out_mean + d1 * CH + j * 4;
    float* av1 = out_var  + d1 * CH + j * 4;

    asm volatile("red.global.add.v4.f32 [%0], {%1, %2, %3, %4};"
                 :: "l"(am0), "f"(m0a.x * w0), "f"(m0a.y * w0), "f"(m0b.x * w0), "f"(m0b.y * w0)
                 : "memory");
    asm volatile("red.global.add.v4.f32 [%0], {%1, %2, %3, %4};"
                 :: "l"(av0), "f"(v0a.x * q0), "f"(v0a.y * q0), "f"(v0b.x * q0), "f"(v0b.y * q0)
                 : "memory");
    asm volatile("red.global.add.v4.f32 [%0], {%1, %2, %3, %4};"
                 :: "l"(am1), "f"(m1a.x * w1), "f"(m1a.y * w1), "f"(m1b.x * w1), "f"(m1b.y * w1)
                 : "memory");
    asm volatile("red.global.add.v4.f32 [%0], {%1, %2, %3, %4};"
                 :: "l"(av1), "f"(v1a.x * q1), "f"(v1a.y * q1), "f"(v1b.x * q1), "f"(v1b.y * q1)
                 : "memory");
}

// ---------------------------------------------------------------------------
// Kernel 4: finalize std: std = sqrt(exp(log_var)+1e-6), fast-math MUFU.
// ---------------------------------------------------------------------------
__global__ __launch_bounds__(256) void finalize_kernel(float4* __restrict__ out_var4) {
    int base = blockIdx.x * 1024 + threadIdx.x;
    #pragma unroll
    for (int t = 0; t < 4; t++) {
        int i = base + t * 256;
        if (i < OUT_ELEMS / 4) {
            float4 x = out_var4[i];
            x.x = __fsqrt_rn(__expf(x.x) + 1e-6f);
            x.y = __fsqrt_rn(__expf(x.y) + 1e-6f);
            x.z = __fsqrt_rn(__expf(x.z) + 1e-6f);
            x.w = __fsqrt_rn(__expf(x.w) + 1e-6f);
            out_var4[i] = x;
        }
    }
}

// ---------------------------------------------------------------------------
extern "C" void kernel_launch(void* const* d_in, const int* in_sizes, int n_in,
                              void* d_out, int out_size)
{
    const float* mean  = (const float*)d_in[0];   // [50000, 64]
    const float* stdv  = (const float*)d_in[1];   // [50000, 64]
    const int*   ei    = (const int*)  d_in[2];   // [2, 800000]
    const float* ew    = (const float*)d_in[3];   // [800000]
    const float* mu_m  = (const float*)d_in[4];
    const float* ls_m  = (const float*)d_in[5];
    const float* eps_m = (const float*)d_in[6];
    const float* mu_s  = (const float*)d_in[7];
    const float* ls_s  = (const float*)d_in[8];
    const float* eps_s = (const float*)d_in[9];

    float* out_mean = (float*)d_out;                   // [50000*64]
    float* out_var  = out_mean + OUT_ELEMS;            // [50000*64]
    float* kl_out   = out_mean + 2 * OUT_ELEMS;        // scalar

    // 1) prep + zero: weights + KL + clear accumulators
    prep_zero_kernel<<<400, 256>>>(mu_m, ls_m, eps_m, mu_s, ls_s, eps_s,
                                   out_mean, kl_out);
    // 2) dual GEMM -> fp16 support tensors
    {
        dim3 grid(GX, 2);
        gemm_kernel<<<grid, 256>>>(mean, stdv);
    }
    // 3) edge scatter (2 edges x both branches per thread)
    {
        int total = HALF_E * 16;                       // 6,400,000 threads
        scatter_kernel<<<total / 512, 512>>>(ei, ew, out_mean, out_var);
    }
    // 4) finalize std
    finalize_kernel<<<782, 256>>>((float4*)out_var);
}

// round 9
// speedup vs baseline: 2.1504x; 1.1631x over previous
#include <cuda_runtime.h>
#include <cuda_fp16.h>
#include <cstdint>

#define N_NODES 50000
#define N_EDGES 800000
#define HALF_E (N_EDGES / 2)
#define CH 64
#define CH4 16
#define OUT_ELEMS (N_NODES * CH)
#define GX 391                            // ceil(50000/128)
#define ZERO_FLOAT4 (OUT_ELEMS * 2 / 4)   // 1,600,000
#define PITCH 72                          // smem pitch in halves (conflict-free LDSM)

// ---- scratch (device globals; no allocation allowed) ----
__device__ float g_w[2][CH * CH];             // reparameterized weights (fp32)
// support tensors in fp16: [branch][node*16 + chunk], chunk = 4 halves (8B)
__device__ uint2 g_suph[2][N_NODES * CH4];

// ---------------------------------------------------------------------------
// Kernel 1: prep + zero. 400 blocks:
//   all blocks: zero a 4096-float4 slice of the output accumulation area
//   blocks 0..15: build W (512 elems each)
//   block 0: reduce KL for both branches
// ---------------------------------------------------------------------------
__global__ __launch_bounds__(256) void prep_zero_kernel(
    const float* __restrict__ mu_m, const float* __restrict__ ls_m,
    const float* __restrict__ eps_m,
    const float* __restrict__ mu_s, const float* __restrict__ ls_s,
    const float* __restrict__ eps_s,
    float* __restrict__ out_base, float* __restrict__ kl_out)
{
    int tid = threadIdx.x;
    int bid = blockIdx.x;

    // zero slice
    {
        float4* out4 = (float4*)out_base;
        float4 z = make_float4(0.f, 0.f, 0.f, 0.f);
        #pragma unroll
        for (int t = 0; t < 16; t++) {
            int i = bid * 4096 + t * 256 + tid;
            if (i < ZERO_FLOAT4) out4[i] = z;
        }
    }

    // W build (blocks 0..15)
    if (bid < 16) {
        int base = bid * 512;
        #pragma unroll
        for (int t = 0; t < 2; t++) {
            int i = base + t * 256 + tid;       // < 8192 covers both branches
            if (i < CH * CH) {
                g_w[0][i] = mu_m[i] + eps_m[i] * expf(ls_m[i]);
            } else {
                int j = i - CH * CH;
                g_w[1][j] = mu_s[j] + eps_s[j] * expf(ls_s[j]);
            }
        }
    }

    // KL (block 0)
    if (bid == 0) {
        __shared__ float sred[256];
        float acc = 0.f;
        for (int i = tid; i < CH * CH; i += 256) {
            float lm = ls_m[i], mm = mu_m[i];
            acc += 0.5f * (expf(2.f * lm) + mm * mm - 2.f * lm - 1.f);
            float lv = ls_s[i], ms = mu_s[i];
            acc += 0.5f * (expf(2.f * lv) + ms * ms - 2.f * lv - 1.f);
        }
        sred[tid] = acc;
        __syncthreads();
        for (int s = 128; s > 0; s >>= 1) {
            if (tid < s) sred[tid] += sred[tid + s];
            __syncthreads();
        }
        if (tid == 0) kl_out[0] = sred[0];
    }
}

// ---------------------------------------------------------------------------
// Kernel 2: HMMA GEMM. 128x64 tile per block, 8 warps, each warp 16 rows.
// X, W staged as fp16 in smem (pitch 72 halves); mma.m16n8k16 f32 accum;
// epilogue converts to fp16 support tensors.
// ---------------------------------------------------------------------------
__global__ __launch_bounds__(256) void gemm_kernel(
    const float* __restrict__ mean, const float* __restrict__ stdv)
{
    __shared__ __half sX[128 * PITCH];   // 18432 B
    __shared__ __half sW[CH * PITCH];    //  9216 B

    int branch = blockIdx.y;
    int row0 = blockIdx.x * 128;
    int tid = threadIdx.x;

    // stage W (64x64): 1024 float4 chunks; 16 lanes per k-row (coalesced)
    {
        const float4* w4 = (const float4*)g_w[branch];
        #pragma unroll
        for (int t = 0; t < 4; t++) {
            int i = t * 256 + tid;          // 0..1023
            int c4 = i & 15, k = i >> 4;
            float4 v = w4[k * CH4 + c4];
            __half2 h0 = __floats2half2_rn(v.x, v.y);
            __half2 h1 = __floats2half2_rn(v.z, v.w);
            *(__half2*)&sW[k * PITCH + c4 * 4]     = h0;
            *(__half2*)&sW[k * PITCH + c4 * 4 + 2] = h1;
        }
    }

    // stage X (128x64): 2048 float4 chunks; 16 lanes per row (coalesced)
    const float4* in4 = (const float4*)(branch ? stdv : mean);
    {
        #pragma unroll
        for (int t = 0; t < 8; t++) {
            int i = t * 256 + tid;          // 0..2047
            int c4 = i & 15, r = i >> 4;
            int node = row0 + r;
            float4 v = make_float4(0.f, 0.f, 0.f, 0.f);
            if (node < N_NODES) v = in4[node * CH4 + c4];
            if (branch) { v.x *= v.x; v.y *= v.y; v.z *= v.z; v.w *= v.w; }
            __half2 h0 = __floats2half2_rn(v.x, v.y);
            __half2 h1 = __floats2half2_rn(v.z, v.w);
            *(__half2*)&sX[r * PITCH + c4 * 4]     = h0;
            *(__half2*)&sX[r * PITCH + c4 * 4 + 2] = h1;
        }
    }
    __syncthreads();

    int w = tid >> 5, lane = tid & 31;

    float acc[8][4];
    #pragma unroll
    for (int nt = 0; nt < 8; nt++)
        #pragma unroll
        for (int c = 0; c < 4; c++) acc[nt][c] = 0.f;

    #pragma unroll
    for (int kk = 0; kk < 4; kk++) {
        // A fragment: 16x16 at rows w*16, k-cols kk*16 (ldmatrix.x4)
        unsigned a0, a1, a2, a3;
        {
            int r = lane & 15, c8 = (lane >> 4) * 8;
            unsigned aaddr = (unsigned)__cvta_generic_to_shared(
                &sX[(w * 16 + r) * PITCH + kk * 16 + c8]);
            asm volatile(
                "ldmatrix.sync.aligned.m8n8.x4.shared.b16 {%0,%1,%2,%3}, [%4];"
                : "=r"(a0), "=r"(a1), "=r"(a2), "=r"(a3) : "r"(aaddr));
        }
        #pragma unroll
        for (int nt = 0; nt < 8; nt++) {
            // B fragment: 16x8 at k-rows kk*16, n-cols nt*8 (ldmatrix.x2.trans)
            unsigned b0, b1;
            {
                unsigned baddr = (unsigned)__cvta_generic_to_shared(
                    &sW[(kk * 16 + (lane & 15)) * PITCH + nt * 8]);
                asm volatile(
                    "ldmatrix.sync.aligned.m8n8.x2.trans.shared.b16 {%0,%1}, [%2];"
                    : "=r"(b0), "=r"(b1) : "r"(baddr));
            }
            asm volatile(
                "mma.sync.aligned.m16n8k16.row.col.f32.f16.f16.f32 "
                "{%0,%1,%2,%3}, {%4,%5,%6,%7}, {%8,%9}, {%0,%1,%2,%3};"
                : "+f"(acc[nt][0]), "+f"(acc[nt][1]),
                  "+f"(acc[nt][2]), "+f"(acc[nt][3])
                : "r"(a0), "r"(a1), "r"(a2), "r"(a3), "r"(b0), "r"(b1));
        }
    }

    // epilogue: acc -> fp16 support tensor
    unsigned* suph = (unsigned*)g_suph[branch];
    int g = lane >> 2, tg = lane & 3;
    int node0 = row0 + w * 16 + g;
    int node1 = node0 + 8;
    #pragma unroll
    for (int nt = 0; nt < 8; nt++) {
        __half2 h0 = __floats2half2_rn(acc[nt][0], acc[nt][1]);
        __half2 h1 = __floats2half2_rn(acc[nt][2], acc[nt][3]);
        int cidx = nt * 4 + tg;              // uint index within 32-uint row
        if (node0 < N_NODES) suph[node0 * 32 + cidx] = *(unsigned*)&h0;
        if (node1 < N_NODES) suph[node1 * 32 + cidx] = *(unsigned*)&h1;
    }
}

// ---------------------------------------------------------------------------
// Kernel 3: edge scatter, TWO edges + both branches per thread.
// fp16 gathers, fp32 vector reductions out.
// ---------------------------------------------------------------------------
__global__ __launch_bounds__(512) void scatter_kernel(
    const int* __restrict__ ei, const float* __restrict__ ew,
    float* __restrict__ out_mean, float* __restrict__ out_var)
{
    int idx = blockIdx.x * 512 + threadIdx.x;          // < HALF_E*16 = 6.4M
    int j = idx & 15;                                  // chunk within row
    int e0 = idx >> 4;                                 // 0..HALF_E-1
    int e1 = e0 + HALF_E;

    // front-batched meta loads (6 independent)
    int   s0 = __ldg(&ei[e0]);
    int   s1 = __ldg(&ei[e1]);
    int   d0 = __ldg(&ei[N_EDGES + e0]);
    int   d1 = __ldg(&ei[N_EDGES + e1]);
    float w0 = __ldg(&ew[e0]);
    float w1 = __ldg(&ew[e1]);

    // 4 independent fp16 gathers (8B each; warp-coalesced 128B rows)
    uint2 m0h = __ldg(&g_suph[0][s0 * CH4 + j]);
    uint2 m1h = __ldg(&g_suph[0][s1 * CH4 + j]);
    uint2 v0h = __ldg(&g_suph[1][s0 * CH4 + j]);
    uint2 v1h = __ldg(&g_suph[1][s1 * CH4 + j]);

    float q0 = w0 * w0, q1 = w1 * w1;

    float2 m0a = __half22float2(*(__half2*)&m0h.x);
    float2 m0b = __half22float2(*(__half2*)&m0h.y);
    float2 m1a = __half22float2(*(__half2*)&m1h.x);
    float2 m1b = __half22float2(*(__half2*)&m1h.y);
    float2 v0a = __half22float2(*(__half2*)&v0h.x);
    float2 v0b = __half22float2(*(__half2*)&v0h.y);
    float2 v1a = __half22float2(*(__half2*)&v1h.x);
    float2 v1b = __half22float2(*(__half2*)&v1h.y);

    float* am0 = out_mean + d0 * CH + j * 4;
    float* av0 = out_var  + d0 * CH + j * 4;
    float* am1 = out_mean + d1 * CH + j * 4;
    float* av1 = out_var  + d1 * CH + j * 4;

    asm volatile("red.global.add.v4.f32 [%0], {%1, %2, %3, %4};"
                 :: "l"(am0), "f"(m0a.x * w0), "f"(m0a.y * w0), "f"(m0b.x * w0), "f"(m0b.y * w0)
                 : "memory");
    asm volatile("red.global.add.v4.f32 [%0], {%1, %2, %3, %4};"
                 :: "l"(av0), "f"(v0a.x * q0), "f"(v0a.y * q0), "f"(v0b.x * q0), "f"(v0b.y * q0)
                 : "memory");
    asm volatile("red.global.add.v4.f32 [%0], {%1, %2, %3, %4};"
                 :: "l"(am1), "f"(m1a.x * w1), "f"(m1a.y * w1), "f"(m1b.x * w1), "f"(m1b.y * w1)
                 : "memory");
    asm volatile("red.global.add.v4.f32 [%0], {%1, %2, %3, %4};"
                 :: "l"(av1), "f"(v1a.x * q1), "f"(v1a.y * q1), "f"(v1b.x * q1), "f"(v1b.y * q1)
                 : "memory");
}

// ---------------------------------------------------------------------------
// Kernel 4: finalize std: std = sqrt(exp(log_var)+1e-6), fast-math MUFU.
// ---------------------------------------------------------------------------
__global__ __launch_bounds__(256) void finalize_kernel(float4* __restrict__ out_var4) {
    int base = blockIdx.x * 1024 + threadIdx.x;
    #pragma unroll
    for (int t = 0; t < 4; t++) {
        int i = base + t * 256;
        if (i < OUT_ELEMS / 4) {
            float4 x = out_var4[i];
            x.x = __fsqrt_rn(__expf(x.x) + 1e-6f);
            x.y = __fsqrt_rn(__expf(x.y) + 1e-6f);
            x.z = __fsqrt_rn(__expf(x.z) + 1e-6f);
            x.w = __fsqrt_rn(__expf(x.w) + 1e-6f);
            out_var4[i] = x;
        }
    }
}

// ---------------------------------------------------------------------------
extern "C" void kernel_launch(void* const* d_in, const int* in_sizes, int n_in,
                              void* d_out, int out_size)
{
    const float* mean  = (const float*)d_in[0];   // [50000, 64]
    const float* stdv  = (const float*)d_in[1];   // [50000, 64]
    const int*   ei    = (const int*)  d_in[2];   // [2, 800000]
    const float* ew    = (const float*)d_in[3];   // [800000]
    const float* mu_m  = (const float*)d_in[4];
    const float* ls_m  = (const float*)d_in[5];
    const float* eps_m = (const float*)d_in[6];
    const float* mu_s  = (const float*)d_in[7];
    const float* ls_s  = (const float*)d_in[8];
    const float* eps_s = (const float*)d_in[9];

    float* out_mean = (float*)d_out;                   // [50000*64]
    float* out_var  = out_mean + OUT_ELEMS;            // [50000*64]
    float* kl_out   = out_mean + 2 * OUT_ELEMS;        // scalar

    // 1) prep + zero: weights + KL + clear accumulators
    prep_zero_kernel<<<400, 256>>>(mu_m, ls_m, eps_m, mu_s, ls_s, eps_s,
                                   out_mean, kl_out);
    // 2) dual HMMA GEMM -> fp16 support tensors
    {
        dim3 grid(GX, 2);
        gemm_kernel<<<grid, 256>>>(mean, stdv);
    }
    // 3) edge scatter (2 edges x both branches per thread)
    {
        int total = HALF_E * 16;                       // 6,400,000 threads
        scatter_kernel<<<total / 512, 512>>>(ei, ew, out_mean, out_var);
    }
    // 4) finalize std
    finalize_kernel<<<782, 256>>>((float4*)out_var);
}

// round 10
// speedup vs baseline: 2.2433x; 1.0432x over previous
#include <cuda_runtime.h>
#include <cuda_fp16.h>
#include <cstdint>

#define N_NODES 50000
#define N_EDGES 800000
#define HALF_E (N_EDGES / 2)
#define CH 64
#define CH4 16
#define OUT_ELEMS (N_NODES * CH)
#define GX 391                            // ceil(50000/128)
#define ZERO_FLOAT4 (OUT_ELEMS * 2 / 4)   // 1,600,000
#define PITCH 72                          // smem pitch in halves (conflict-free LDSM)

// ---- scratch (device globals; no allocation allowed) ----
// support tensors in fp16: [branch][node*16 + chunk], chunk = 4 halves (8B)
__device__ uint2 g_suph[2][N_NODES * CH4];

// ---------------------------------------------------------------------------
// Kernel 1 (fused): per block —
//   (a) zero a 2048-float4 slice of the output accumulation area,
//   (b) build this branch's reparameterized W directly into fp16 smem,
//   (c) block (0,0) reduces KL for both branches,
//   (d) HMMA GEMM: 128x64 tile, 8 warps, mma.m16n8k16, f32 accum,
//       epilogue -> fp16 support tensors.
//   branch 0: sup_mean = mean @ W_mean ; branch 1: sup_var = (std^2) @ W_var
// ---------------------------------------------------------------------------
__global__ __launch_bounds__(256) void gemm_fused_kernel(
    const float* __restrict__ mean, const float* __restrict__ stdv,
    const float* __restrict__ mu_m, const float* __restrict__ ls_m,
    const float* __restrict__ eps_m,
    const float* __restrict__ mu_s, const float* __restrict__ ls_s,
    const float* __restrict__ eps_s,
    float* __restrict__ out_base, float* __restrict__ kl_out)
{
    __shared__ __half sX[128 * PITCH];   // 18432 B
    __shared__ __half sW[CH * PITCH];    //  9216 B

    int branch = blockIdx.y;
    int row0 = blockIdx.x * 128;
    int tid = threadIdx.x;
    int bid = blockIdx.x + GX * branch;  // 0..781

    // (a) zero 2048 float4 of the output accumulation area
    {
        float4* out4 = (float4*)out_base;
        float4 z = make_float4(0.f, 0.f, 0.f, 0.f);
        #pragma unroll
        for (int t = 0; t < 8; t++) {
            int i = bid * 2048 + t * 256 + tid;
            if (i < ZERO_FLOAT4) out4[i] = z;
        }
    }

    // (b) build this branch's W directly into fp16 smem
    {
        const float* mu  = branch ? mu_s  : mu_m;
        const float* ls  = branch ? ls_s  : ls_m;
        const float* eps = branch ? eps_s : eps_m;
        #pragma unroll
        for (int t = 0; t < 16; t++) {
            int i = t * 256 + tid;           // 0..4095
            int k = i >> 6, c = i & 63;
            float wv = mu[i] + eps[i] * expf(ls[i]);
            sW[k * PITCH + c] = __float2half_rn(wv);
        }
    }

    // (c) KL: block (0,0) only, both branches
    if (blockIdx.x == 0 && branch == 0) {
        __shared__ float sred[256];
        float acc = 0.f;
        for (int i = tid; i < CH * CH; i += 256) {
            float lm = ls_m[i], mm = mu_m[i];
            acc += 0.5f * (expf(2.f * lm) + mm * mm - 2.f * lm - 1.f);
            float lv = ls_s[i], ms = mu_s[i];
            acc += 0.5f * (expf(2.f * lv) + ms * ms - 2.f * lv - 1.f);
        }
        sred[tid] = acc;
        __syncthreads();
        for (int s = 128; s > 0; s >>= 1) {
            if (tid < s) sred[tid] += sred[tid + s];
            __syncthreads();
        }
        if (tid == 0) kl_out[0] = sred[0];
    }

    // stage X (128x64): 2048 float4 chunks; 16 lanes per row (coalesced)
    const float4* in4 = (const float4*)(branch ? stdv : mean);
    {
        #pragma unroll
        for (int t = 0; t < 8; t++) {
            int i = t * 256 + tid;          // 0..2047
            int c4 = i & 15, r = i >> 4;
            int node = row0 + r;
            float4 v = make_float4(0.f, 0.f, 0.f, 0.f);
            if (node < N_NODES) v = in4[node * CH4 + c4];
            if (branch) { v.x *= v.x; v.y *= v.y; v.z *= v.z; v.w *= v.w; }
            __half2 h0 = __floats2half2_rn(v.x, v.y);
            __half2 h1 = __floats2half2_rn(v.z, v.w);
            *(__half2*)&sX[r * PITCH + c4 * 4]     = h0;
            *(__half2*)&sX[r * PITCH + c4 * 4 + 2] = h1;
        }
    }
    __syncthreads();

    int w = tid >> 5, lane = tid & 31;

    float acc[8][4];
    #pragma unroll
    for (int nt = 0; nt < 8; nt++)
        #pragma unroll
        for (int c = 0; c < 4; c++) acc[nt][c] = 0.f;

    #pragma unroll
    for (int kk = 0; kk < 4; kk++) {
        // A fragment: 16x16 at rows w*16, k-cols kk*16 (ldmatrix.x4)
        unsigned a0, a1, a2, a3;
        {
            int r = lane & 15, c8 = (lane >> 4) * 8;
            unsigned aaddr = (unsigned)__cvta_generic_to_shared(
                &sX[(w * 16 + r) * PITCH + kk * 16 + c8]);
            asm volatile(
                "ldmatrix.sync.aligned.m8n8.x4.shared.b16 {%0,%1,%2,%3}, [%4];"
                : "=r"(a0), "=r"(a1), "=r"(a2), "=r"(a3) : "r"(aaddr));
        }
        #pragma unroll
        for (int nt = 0; nt < 8; nt++) {
            // B fragment: 16x8 at k-rows kk*16, n-cols nt*8 (ldmatrix.x2.trans)
            unsigned b0, b1;
            {
                unsigned baddr = (unsigned)__cvta_generic_to_shared(
                    &sW[(kk * 16 + (lane & 15)) * PITCH + nt * 8]);
                asm volatile(
                    "ldmatrix.sync.aligned.m8n8.x2.trans.shared.b16 {%0,%1}, [%2];"
                    : "=r"(b0), "=r"(b1) : "r"(baddr));
            }
            asm volatile(
                "mma.sync.aligned.m16n8k16.row.col.f32.f16.f16.f32 "
                "{%0,%1,%2,%3}, {%4,%5,%6,%7}, {%8,%9}, {%0,%1,%2,%3};"
                : "+f"(acc[nt][0]), "+f"(acc[nt][1]),
                  "+f"(acc[nt][2]), "+f"(acc[nt][3])
                : "r"(a0), "r"(a1), "r"(a2), "r"(a3), "r"(b0), "r"(b1));
        }
    }

    // epilogue: acc -> fp16 support tensor
    unsigned* suph = (unsigned*)g_suph[branch];
    int g = lane >> 2, tg = lane & 3;
    int node0 = row0 + w * 16 + g;
    int node1 = node0 + 8;
    #pragma unroll
    for (int nt = 0; nt < 8; nt++) {
        __half2 h0 = __floats2half2_rn(acc[nt][0], acc[nt][1]);
        __half2 h1 = __floats2half2_rn(acc[nt][2], acc[nt][3]);
        int cidx = nt * 4 + tg;              // uint index within 32-uint row
        if (node0 < N_NODES) suph[node0 * 32 + cidx] = *(unsigned*)&h0;
        if (node1 < N_NODES) suph[node1 * 32 + cidx] = *(unsigned*)&h1;
    }
}

// ---------------------------------------------------------------------------
// Kernel 2: edge scatter, TWO edges + both branches per thread.
// fp16 gathers, fp32 vector reductions out.
// ---------------------------------------------------------------------------
__global__ __launch_bounds__(512) void scatter_kernel(
    const int* __restrict__ ei, const float* __restrict__ ew,
    float* __restrict__ out_mean, float* __restrict__ out_var)
{
    int idx = blockIdx.x * 512 + threadIdx.x;          // < HALF_E*16 = 6.4M
    int j = idx & 15;                                  // chunk within row
    int e0 = idx >> 4;                                 // 0..HALF_E-1
    int e1 = e0 + HALF_E;

    // front-batched meta loads (6 independent)
    int   s0 = __ldg(&ei[e0]);
    int   s1 = __ldg(&ei[e1]);
    int   d0 = __ldg(&ei[N_EDGES + e0]);
    int   d1 = __ldg(&ei[N_EDGES + e1]);
    float w0 = __ldg(&ew[e0]);
    float w1 = __ldg(&ew[e1]);

    // 4 independent fp16 gathers (8B each; warp-coalesced 128B rows)
    uint2 m0h = __ldg(&g_suph[0][s0 * CH4 + j]);
    uint2 m1h = __ldg(&g_suph[0][s1 * CH4 + j]);
    uint2 v0h = __ldg(&g_suph[1][s0 * CH4 + j]);
    uint2 v1h = __ldg(&g_suph[1][s1 * CH4 + j]);

    float q0 = w0 * w0, q1 = w1 * w1;

    float2 m0a = __half22float2(*(__half2*)&m0h.x);
    float2 m0b = __half22float2(*(__half2*)&m0h.y);
    float2 m1a = __half22float2(*(__half2*)&m1h.x);
    float2 m1b = __half22float2(*(__half2*)&m1h.y);
    float2 v0a = __half22float2(*(__half2*)&v0h.x);
    float2 v0b = __half22float2(*(__half2*)&v0h.y);
    float2 v1a = __half22float2(*(__half2*)&v1h.x);
    float2 v1b = __half22float2(*(__half2*)&v1h.y);

    float* am0 = out_mean + d0 * CH + j * 4;
    float* av0 = out_var  + d0 * CH + j * 4;
    float* am1 = out_mean + d1 * CH + j * 4;
    float* av1 = out_var  + d1 * CH + j * 4;

    asm volatile("red.global.add.v4.f32 [%0], {%1, %2, %3, %4};"
                 :: "l"(am0), "f"(m0a.x * w0), "f"(m0a.y * w0), "f"(m0b.x * w0), "f"(m0b.y * w0)
                 : "memory");
    asm volatile("red.global.add.v4.f32 [%0], {%1, %2, %3, %4};"
                 :: "l"(av0), "f"(v0a.x * q0), "f"(v0a.y * q0), "f"(v0b.x * q0), "f"(v0b.y * q0)
                 : "memory");
    asm volatile("red.global.add.v4.f32 [%0], {%1, %2, %3, %4};"
                 :: "l"(am1), "f"(m1a.x * w1), "f"(m1a.y * w1), "f"(m1b.x * w1), "f"(m1b.y * w1)
                 : "memory");
    asm volatile("red.global.add.v4.f32 [%0], {%1, %2, %3, %4};"
                 :: "l"(av1), "f"(v1a.x * q1), "f"(v1a.y * q1), "f"(v1b.x * q1), "f"(v1b.y * q1)
                 : "memory");
}

// ---------------------------------------------------------------------------
// Kernel 3: finalize std: std = sqrt(exp(log_var)+1e-6), fast-math MUFU.
// ---------------------------------------------------------------------------
__global__ __launch_bounds__(256) void finalize_kernel(float4* __restrict__ out_var4) {
    int base = blockIdx.x * 1024 + threadIdx.x;
    #pragma unroll
    for (int t = 0; t < 4; t++) {
        int i = base + t * 256;
        if (i < OUT_ELEMS / 4) {
            float4 x = out_var4[i];
            x.x = __fsqrt_rn(__expf(x.x) + 1e-6f);
            x.y = __fsqrt_rn(__expf(x.y) + 1e-6f);
            x.z = __fsqrt_rn(__expf(x.z) + 1e-6f);
            x.w = __fsqrt_rn(__expf(x.w) + 1e-6f);
            out_var4[i] = x;
        }
    }
}

// ---------------------------------------------------------------------------
extern "C" void kernel_launch(void* const* d_in, const int* in_sizes, int n_in,
                              void* d_out, int out_size)
{
    const float* mean  = (const float*)d_in[0];   // [50000, 64]
    const float* stdv  = (const float*)d_in[1];   // [50000, 64]
    const int*   ei    = (const int*)  d_in[2];   // [2, 800000]
    const float* ew    = (const float*)d_in[3];   // [800000]
    const float* mu_m  = (const float*)d_in[4];
    const float* ls_m  = (const float*)d_in[5];
    const float* eps_m = (const float*)d_in[6];
    const float* mu_s  = (const float*)d_in[7];
    const float* ls_s  = (const float*)d_in[8];
    const float* eps_s = (const float*)d_in[9];

    float* out_mean = (float*)d_out;                   // [50000*64]
    float* out_var  = out_mean + OUT_ELEMS;            // [50000*64]
    float* kl_out   = out_mean + 2 * OUT_ELEMS;        // scalar

    // 1) fused: zero + W build + KL + dual HMMA GEMM
    {
        dim3 grid(GX, 2);
        gemm_fused_kernel<<<grid, 256>>>(mean, stdv,
                                         mu_m, ls_m, eps_m,
                                         mu_s, ls_s, eps_s,
                                         out_mean, kl_out);
    }
    // 2) edge scatter (2 edges x both branches per thread)
    {
        int total = HALF_E * 16;                       // 6,400,000 threads
        scatter_kernel<<<total / 512, 512>>>(ei, ew, out_mean, out_var);
    }
    // 3) finalize std
    finalize_kernel<<<782, 256>>>((float4*)out_var);
}